// round 12
// baseline (speedup 1.0000x reference)
#include <cuda_runtime.h>
#include <cuda_fp16.h>
#include <cstddef>
#include <cstdint>

#define Bsz   1024
#define DF    2048
#define DIM   128
#define CC    8192
#define PP    8
#define NNq   4
#define NC    (NNq * CC)            // 32768
#define PC    (PP * CC)             // 65536
#define SIMW  (Bsz + PP + NNq * (CC - 1))  // 33796
#define SPLITK 16

static constexpr size_t OFF_SIM  = 0;
static constexpr size_t OFF_LAB  = (size_t)Bsz * SIMW;
static constexpr size_t OFF_LQ   = OFF_LAB + (size_t)Bsz * SIMW;
static constexpr size_t OFF_LK   = OFF_LQ + (size_t)Bsz * CC;
static constexpr size_t OFF_NQ2  = OFF_LK + (size_t)Bsz * CC;
static constexpr size_t OFF_PQ2  = OFF_NQ2 + (size_t)DIM * NC;
static constexpr size_t OFF_NPTR = OFF_PQ2 + (size_t)DIM * PC;
static constexpr size_t OFF_PPTR = OFF_NPTR + CC;

// ---------------- device scratch (16B-aligned for cp.async) ---------------
__device__ __align__(16) float  g_Hq[(size_t)Bsz * DF];
__device__ __align__(16) float  g_Hk[(size_t)Bsz * DF];
__device__ __align__(16) __half g_midqH[(size_t)Bsz * DF];
__device__ __align__(16) __half g_midkH[(size_t)Bsz * DF];
__device__ __align__(16) __half g_HqH[(size_t)Bsz * DF];     // relu(BN(H)) half
__device__ __align__(16) __half g_HkH[(size_t)Bsz * DF];
__device__ __align__(16) __half g_W1T[(size_t)DF * DF];      // [N][K] half
__device__ __align__(16) __half g_WlinT[(size_t)CC * DF];
__device__ __align__(16) __half g_W2T[(size_t)DIM * DF];
__device__ __align__(16) __half g_negT[(size_t)NC * DIM];
__device__ float g_scq[DF], g_shq[DF], g_sck[DF], g_shk[DF];
__device__ float g_featq[(size_t)Bsz * DIM];
__device__ float g_featk[(size_t)Bsz * DIM];
__device__ __align__(16) __half g_featqH[(size_t)Bsz * DIM];
__device__ __align__(16) __half g_featkH[(size_t)Bsz * DIM];
__device__ float g_fpart[(size_t)2 * SPLITK * Bsz * DIM];
__device__ int   g_rank[Bsz];
__device__ int   g_cntb[Bsz];

// ---------------- helpers -------------------------------------------------
__device__ __forceinline__ void mma_f16(float c[4], const unsigned a[4],
                                        const unsigned b[2]) {
    asm volatile(
        "mma.sync.aligned.m16n8k16.row.col.f32.f16.f16.f32 "
        "{%0,%1,%2,%3}, {%4,%5,%6,%7}, {%8,%9}, {%0,%1,%2,%3};"
        : "+f"(c[0]), "+f"(c[1]), "+f"(c[2]), "+f"(c[3])
        : "r"(a[0]), "r"(a[1]), "r"(a[2]), "r"(a[3]), "r"(b[0]), "r"(b[1]));
}

__device__ __forceinline__ void ldsm_x4(unsigned r[4], uint32_t addr) {
    asm volatile("ldmatrix.sync.aligned.m8n8.x4.shared.b16 {%0,%1,%2,%3}, [%4];"
                 : "=r"(r[0]), "=r"(r[1]), "=r"(r[2]), "=r"(r[3]) : "r"(addr));
}
// B stored [N][K]: mma b-frag wants stored(n=l>>2, k=2(l&3)+{0,1}) — the
// NON-trans ldmatrix mapping.
__device__ __forceinline__ void ldsm_x2(unsigned r[2], uint32_t addr) {
    asm volatile("ldmatrix.sync.aligned.m8n8.x2.shared.b16 {%0,%1}, [%2];"
                 : "=r"(r[0]), "=r"(r[1]) : "r"(addr));
}

__device__ __forceinline__ void cpa16(uint32_t saddr, const void* g) {
    asm volatile("cp.async.cg.shared.global [%0], [%1], 16;\n"
                 :: "r"(saddr), "l"(g));
}
#define CP_COMMIT() asm volatile("cp.async.commit_group;\n" ::: "memory")
#define CP_WAIT1()  asm volatile("cp.async.wait_group 1;\n" ::: "memory")
#define CP_WAIT0()  asm volatile("cp.async.wait_group 0;\n" ::: "memory")

// ---------------- FP16 tensor-core GEMM, BK=64, double-buffered -----------
// 128x128 tile, BK=64 (halfs: 128B/row), 256 threads (8 warps, 64x32 each).
// A [M][K] half, Bt [N][K] half (K-major; shared staging path).
// Smem rows padded to 72 halfs (144B pitch): ldmatrix phase banks
// 36r mod 32 = 4r mod 32 -> {0,4,..,28}: conflict-free; rows 16B-aligned.
// 2 stages x 73.7KB dynamic smem; 2 CTAs/SM.
// MODE 0: C = A@B + bias; z selects (A0,C0)/(A1,C1)
// MODE 2: split-K partial: z = qk*SPLITK + sk; C = C0 + z*Bsz*DIM
// MODE 3: plain; also writes labels_batch (lkk[n]==lqq[m]) into Lab
// MODE 4: neg scatter skipping lqq[m]'s NNq cols; writes 0.0f into Lab
#define BK    64
#define HSTR  72
#define TILEH (128 * HSTR)        // halfs per tile
#define STAGEH (2 * TILEH)        // halfs per stage (A + B)
template <int MODE>
__global__ __launch_bounds__(256, 2) void hgemm_k(
    const __half* __restrict__ A0, const __half* __restrict__ A1,
    const __half* __restrict__ Bt, const float* __restrict__ bias,
    float* __restrict__ C0, float* __restrict__ C1,
    int K, int ldc,
    const int* __restrict__ lqq, const int* __restrict__ lkk,
    float* __restrict__ Lab)
{
    extern __shared__ __align__(16) __half smem[];

    const int tid   = threadIdx.x;
    const int mBase = blockIdx.y * 128;
    const int nBase = blockIdx.x * 128;
    const int lane  = tid & 31;
    const int warp  = tid >> 5;
    const int g     = lane >> 2;
    const int tig   = lane & 3;
    const int wm    = (warp & 1) * 64;
    const int wn    = (warp >> 1) * 32;

    int kBeg = 0, kEnd = K;
    const __half* A;
    float* Cc;
    if (MODE == 2) {
        int qk  = blockIdx.z >> 4;
        int skc = blockIdx.z & 15;
        kBeg = skc * (K / SPLITK);
        kEnd = kBeg + K / SPLITK;
        A  = qk ? A1 : A0;
        Cc = C0 + (size_t)blockIdx.z * ((size_t)Bsz * DIM);
    } else {
        A  = blockIdx.z ? A1 : A0;
        Cc = blockIdx.z ? C1 : C0;
    }

    uint32_t sbase = (uint32_t)__cvta_generic_to_shared(smem);

    // ldmatrix per-lane address components
    const int a_row = wm + (lane & 7) + ((lane >> 3) & 1) * 8;  // + mt*16
    const int a_kof = (lane >> 4) << 3;                         // 0 or 8
    const int b_row = wn + (lane & 7);                          // + nt*8
    const int b_kof = ((lane >> 3) & 1) << 3;                   // 0 or 8

    // staging: each row = 64 halfs = 8 x 16B chunks; 2 threads/row, 4 each
    const int sr = tid >> 1;
    const int cb = (tid & 1) * 4;
    auto load_tiles = [&](int s, int kpos) {
        const __half* srcA = A  + (size_t)(mBase + sr) * K + kpos;
        const __half* srcB = Bt + (size_t)(nBase + sr) * K + kpos;
        uint32_t rowA = sbase + (uint32_t)((s * STAGEH + sr * HSTR) * 2);
        uint32_t rowB = rowA + (uint32_t)(TILEH * 2);
        #pragma unroll
        for (int i = 0; i < 4; i++) {
            int c = cb + i;
            cpa16(rowA + (uint32_t)(c * 16), srcA + c * 8);
            cpa16(rowB + (uint32_t)(c * 16), srcB + c * 8);
        }
    };

    float acc[4][4][4] = {};

    const int nIter = (kEnd - kBeg) / BK;
    load_tiles(0, kBeg);
    CP_COMMIT();

    for (int it = 0; it < nIter; ++it) {
        int s = it & 1;
        if (it + 1 < nIter) {
            load_tiles(s ^ 1, kBeg + (it + 1) * BK);
            CP_COMMIT();
            CP_WAIT1();
        } else {
            CP_WAIT0();
        }
        __syncthreads();

        const uint32_t aS = sbase + (uint32_t)(s * STAGEH * 2);
        const uint32_t bS = aS + (uint32_t)(TILEH * 2);
        #pragma unroll
        for (int kk = 0; kk < BK; kk += 16) {
            unsigned af[4][4], bf[4][2];
            #pragma unroll
            for (int mt = 0; mt < 4; mt++)
                ldsm_x4(af[mt],
                        aS + (uint32_t)(((a_row + mt * 16) * HSTR + kk + a_kof) * 2));
            #pragma unroll
            for (int nt = 0; nt < 4; nt++)
                ldsm_x2(bf[nt],
                        bS + (uint32_t)(((b_row + nt * 8) * HSTR + kk + b_kof) * 2));
            #pragma unroll
            for (int mt = 0; mt < 4; mt++)
                #pragma unroll
                for (int nt = 0; nt < 4; nt++)
                    mma_f16(acc[mt][nt], af[mt], bf[nt]);
        }
        __syncthreads();
    }

    // ---- epilogue ----
    #pragma unroll
    for (int mt = 0; mt < 4; mt++) {
        int r0 = mBase + wm + mt * 16 + g;
        int r1 = r0 + 8;
        int la0 = 0, la1 = 0, lb0 = 0, lb1 = 0;
        if (MODE == 4) { la0 = lqq[r0] * NNq; la1 = lqq[r1] * NNq; }
        if (MODE == 3) { lb0 = lqq[r0]; lb1 = lqq[r1]; }
        #pragma unroll
        for (int nt = 0; nt < 4; nt++) {
            int c = nBase + wn + nt * 8 + 2 * tig;
            const float* a4 = acc[mt][nt];
            if (MODE == 4) {
                int n0 = c, n1 = c + 1;
                if (n0 < la0) {
                    Cc [(size_t)r0 * ldc + n0] = a4[0];
                    Lab[(size_t)r0 * ldc + n0] = 0.f;
                } else if (n0 >= la0 + NNq) {
                    Cc [(size_t)r0 * ldc + n0 - NNq] = a4[0];
                    Lab[(size_t)r0 * ldc + n0 - NNq] = 0.f;
                }
                if (n1 < la0) {
                    Cc [(size_t)r0 * ldc + n1] = a4[1];
                    Lab[(size_t)r0 * ldc + n1] = 0.f;
                } else if (n1 >= la0 + NNq) {
                    Cc [(size_t)r0 * ldc + n1 - NNq] = a4[1];
                    Lab[(size_t)r0 * ldc + n1 - NNq] = 0.f;
                }
                if (n0 < la1) {
                    Cc [(size_t)r1 * ldc + n0] = a4[2];
                    Lab[(size_t)r1 * ldc + n0] = 0.f;
                } else if (n0 >= la1 + NNq) {
                    Cc [(size_t)r1 * ldc + n0 - NNq] = a4[2];
                    Lab[(size_t)r1 * ldc + n0 - NNq] = 0.f;
                }
                if (n1 < la1) {
                    Cc [(size_t)r1 * ldc + n1] = a4[3];
                    Lab[(size_t)r1 * ldc + n1] = 0.f;
                } else if (n1 >= la1 + NNq) {
                    Cc [(size_t)r1 * ldc + n1 - NNq] = a4[3];
                    Lab[(size_t)r1 * ldc + n1 - NNq] = 0.f;
                }
            } else {
                float bx = 0.f, by = 0.f;
                if (MODE == 0) { bx = bias[c]; by = bias[c + 1]; }
                float2 v0 = { a4[0] + bx, a4[1] + by };
                float2 v1 = { a4[2] + bx, a4[3] + by };
                *(float2*)(Cc + (size_t)r0 * ldc + c) = v0;
                *(float2*)(Cc + (size_t)r1 * ldc + c) = v1;
                if (MODE == 3) {
                    int k0c = lkk[c], k1c = lkk[c + 1];
                    float2 l0 = { (k0c == lb0) ? 1.f : 0.f,
                                  (k1c == lb0) ? 1.f : 0.f };
                    float2 l1 = { (k0c == lb1) ? 1.f : 0.f,
                                  (k1c == lb1) ? 1.f : 0.f };
                    *(float2*)(Lab + (size_t)r0 * ldc + c) = l0;
                    *(float2*)(Lab + (size_t)r1 * ldc + c) = l1;
                }
            }
        }
    }
}

// ---------------- prep: fp32 -> fp16 (8 / thread; q/k via z) ---------------
__global__ void cvt_half_k(const float* __restrict__ in0, const float* __restrict__ in1,
                           __half* __restrict__ o0, __half* __restrict__ o1, int n8)
{
    const float* in = blockIdx.z ? in1 : in0;
    __half* o = blockIdx.z ? o1 : o0;
    int i = blockIdx.x * blockDim.x + threadIdx.x;
    if (i >= n8) return;
    float4 a = ((const float4*)in)[i * 2];
    float4 b = ((const float4*)in)[i * 2 + 1];
    __half h[8];
    h[0] = __float2half_rn(a.x); h[1] = __float2half_rn(a.y);
    h[2] = __float2half_rn(a.z); h[3] = __float2half_rn(a.w);
    h[4] = __float2half_rn(b.x); h[5] = __float2half_rn(b.y);
    h[6] = __float2half_rn(b.z); h[7] = __float2half_rn(b.w);
    ((uint4*)o)[i] = *(const uint4*)h;
}

// ---------------- prep: transpose fp32 [R][C] -> half [C][R] ---------------
__global__ void transpose_half_k(const float* __restrict__ in, __half* __restrict__ out,
                                 int R, int C)
{
    __shared__ float t[32][33];
    int cx = blockIdx.x * 32 + threadIdx.x;
    int ry = blockIdx.y * 32 + threadIdx.y;
    #pragma unroll
    for (int j = 0; j < 32; j += 8)
        t[threadIdx.y + j][threadIdx.x] = in[(size_t)(ry + j) * C + cx];
    __syncthreads();
    int cx2 = blockIdx.y * 32 + threadIdx.x;
    int ry2 = blockIdx.x * 32 + threadIdx.y;
    #pragma unroll
    for (int j = 0; j < 32; j += 8)
        out[(size_t)(ry2 + j) * R + cx2] = __float2half_rn(t[threadIdx.x][threadIdx.y + j]);
}

// ---------------- BN stats -------------------------------------------------
__global__ void bn_stats_k(const float* __restrict__ Hq, const float* __restrict__ Hk,
                           const float* __restrict__ gamma, const float* __restrict__ beta,
                           float* __restrict__ scq, float* __restrict__ shq,
                           float* __restrict__ sck, float* __restrict__ shk)
{
    const float* H = blockIdx.z ? Hk : Hq;
    float* scale = blockIdx.z ? sck : scq;
    float* shift = blockIdx.z ? shk : shq;
    int f = blockIdx.x * 32 + threadIdx.x;
    float s = 0.f, ss = 0.f;
    for (int r = threadIdx.y; r < Bsz; r += 32) {
        float v = H[(size_t)r * DF + f];
        s += v; ss += v * v;
    }
    __shared__ float sh_s[32][33], sh_ss[32][33];
    sh_s[threadIdx.y][threadIdx.x]  = s;
    sh_ss[threadIdx.y][threadIdx.x] = ss;
    __syncthreads();
    if (threadIdx.y == 0) {
        #pragma unroll
        for (int y = 1; y < 32; y++) {
            s += sh_s[y][threadIdx.x]; ss += sh_ss[y][threadIdx.x];
        }
        float mu  = s * (1.f / Bsz);
        float var = ss * (1.f / Bsz) - mu * mu;
        float rst = rsqrtf(var + 1e-5f);
        float scv = rst * gamma[f];
        scale[f] = scv;
        shift[f] = beta[f] - mu * scv;
    }
}

// ---------------- BN apply + relu -> half ----------------------------------
__global__ void bnrelu_half_k(const float* __restrict__ Hq, const float* __restrict__ Hk,
                              __half* __restrict__ Rq, __half* __restrict__ Rk)
{
    const float* H = blockIdx.z ? Hk : Hq;
    __half* R = blockIdx.z ? Rk : Rq;
    const float* sc = blockIdx.z ? g_sck : g_scq;
    const float* sh = blockIdx.z ? g_shk : g_shq;
    int i = blockIdx.x * blockDim.x + threadIdx.x;   // 8-float group
    int f = (i * 8) & (DF - 1);
    float4 a = ((const float4*)H)[i * 2];
    float4 b = ((const float4*)H)[i * 2 + 1];
    float4 sa = *(const float4*)(sc + f);
    float4 sb = *(const float4*)(sc + f + 4);
    float4 ha = *(const float4*)(sh + f);
    float4 hb = *(const float4*)(sh + f + 4);
    __half h[8];
    h[0] = __float2half_rn(fmaxf(fmaf(a.x, sa.x, ha.x), 0.f));
    h[1] = __float2half_rn(fmaxf(fmaf(a.y, sa.y, ha.y), 0.f));
    h[2] = __float2half_rn(fmaxf(fmaf(a.z, sa.z, ha.z), 0.f));
    h[3] = __float2half_rn(fmaxf(fmaf(a.w, sa.w, ha.w), 0.f));
    h[4] = __float2half_rn(fmaxf(fmaf(b.x, sb.x, hb.x), 0.f));
    h[5] = __float2half_rn(fmaxf(fmaf(b.y, sb.y, hb.y), 0.f));
    h[6] = __float2half_rn(fmaxf(fmaf(b.z, sb.z, hb.z), 0.f));
    h[7] = __float2half_rn(fmaxf(fmaf(b.w, sb.w, hb.w), 0.f));
    ((uint4*)R)[i] = *(const uint4*)h;
}

// ---------------- split-K reduce + bias + l2norm ---------------------------
__global__ void reduce_l2_k(const float* __restrict__ b2)
{
    int qk = blockIdx.y, b = blockIdx.x, d = threadIdx.x;  // d: 0..127
    const float* part = g_fpart + (size_t)qk * SPLITK * Bsz * DIM;
    float v = b2[d];
    #pragma unroll
    for (int s = 0; s < SPLITK; s++)
        v += part[(size_t)s * Bsz * DIM + (size_t)b * DIM + d];
    float ss = v * v;
    #pragma unroll
    for (int o = 16; o; o >>= 1) ss += __shfl_xor_sync(0xffffffffu, ss, o);
    __shared__ float ws[4];
    if ((d & 31) == 0) ws[d >> 5] = ss;
    __syncthreads();
    ss = ws[0] + ws[1] + ws[2] + ws[3];
    float inv = 1.f / fmaxf(sqrtf(ss), 1e-12f);
    float vn = v * inv;
    if (qk) {
        g_featk[(size_t)b * DIM + d] = vn;
        g_featkH[(size_t)b * DIM + d] = __float2half_rn(vn);
    } else {
        g_featq[(size_t)b * DIM + d] = vn;
        g_featqH[(size_t)b * DIM + d] = __float2half_rn(vn);
    }
}

// ---------------- pos_list (+ ones into labels) ----------------------------
__global__ void pos_k(const int* __restrict__ lq, const float* __restrict__ posq,
                      float* __restrict__ out)
{
    int b = blockIdx.x, tid = threadIdx.x;
    __shared__ float fr[DIM];
    if (tid < DIM) fr[tid] = g_featq[(size_t)b * DIM + tid];
    __syncthreads();
    int w = tid >> 5, lane = tid & 31;
    int col = lq[b] * PP + w;
    float s = 0.f;
    for (int d = lane; d < DIM; d += 32)
        s += fr[d] * posq[(size_t)d * PC + col];
    #pragma unroll
    for (int o = 16; o; o >>= 1) s += __shfl_down_sync(0xffffffffu, s, o);
    if (lane == 0) {
        out[OFF_SIM + (size_t)b * SIMW + Bsz + w] = s;
        out[OFF_LAB + (size_t)b * SIMW + Bsz + w] = 1.f;
    }
}

// ---------------- occurrence rank + count (warp-per-row) -------------------
__global__ void rank_k(const int* __restrict__ lk)
{
    __shared__ int sl[Bsz];
    int t = threadIdx.y * 32 + threadIdx.x;
    for (int i = t; i < Bsz; i += 1024) sl[i] = lk[i];
    __syncthreads();
    int b = blockIdx.x * 32 + threadIdx.y;
    int lab = sl[b];
    int r = 0, c = 0;
    for (int j = threadIdx.x; j < Bsz; j += 32) {
        int e = (sl[j] == lab);
        c += e;
        r += e & (j < b);
    }
    #pragma unroll
    for (int o = 16; o; o >>= 1) {
        c += __shfl_down_sync(0xffffffffu, c, o);
        r += __shfl_down_sync(0xffffffffu, r, o);
    }
    if (threadIdx.x == 0) { g_rank[b] = r; g_cntb[b] = c; }
}

// ---------------- ptr outputs (warp-per-class) -----------------------------
__global__ void ptr_k(const int* __restrict__ lk, const int* __restrict__ nptr,
                      const int* __restrict__ pptr, float* __restrict__ out)
{
    __shared__ int sl[Bsz];
    for (int i = threadIdx.x; i < Bsz; i += 256) sl[i] = lk[i];
    __syncthreads();
    int w = threadIdx.x >> 5, lane = threadIdx.x & 31;
    int c = blockIdx.x * 8 + w;
    int cnt = 0;
    for (int j = lane; j < Bsz; j += 32) cnt += (sl[j] == c);
    #pragma unroll
    for (int o = 16; o; o >>= 1) cnt += __shfl_down_sync(0xffffffffu, cnt, o);
    if (lane == 0) {
        out[OFF_NPTR + c] = (float)((nptr[c] + cnt) % NNq);
        out[OFF_PPTR + c] = (float)((pptr[c] + cnt) % PP);
    }
}

// ---------------- queue overwrite ------------------------------------------
__global__ void queue_update_k(const int* __restrict__ lk, const int* __restrict__ nptr,
                               const int* __restrict__ pptr, float* __restrict__ out)
{
    int b = blockIdx.x;
    int d = threadIdx.x;   // 128
    int lab = lk[b];
    int r = g_rank[b];
    int c = g_cntb[b];
    float v = g_featk[(size_t)b * DIM + d];
    if (r >= c - NNq) {
        int slot = (nptr[lab] + r) % NNq;
        out[OFF_NQ2 + (size_t)d * NC + lab * NNq + slot] = v;
    }
    if (r >= c - PP) {
        int slot = (pptr[lab] + r) % PP;
        out[OFF_PQ2 + (size_t)d * PC + lab * PP + slot] = v;
    }
}

// ---------------- host launcher --------------------------------------------
static void* symp(const void* sym) {
    void* p = nullptr;
    cudaGetSymbolAddress(&p, sym);
    return p;
}

extern "C" void kernel_launch(void* const* d_in, const int* in_sizes, int n_in,
                              void* d_out, int out_size)
{
    (void)in_sizes; (void)n_in; (void)out_size;
    const float* midq  = (const float*)d_in[0];
    const float* midk  = (const float*)d_in[1];
    const int*   lq    = (const int*)d_in[2];
    const int*   lk    = (const int*)d_in[3];
    const float* W1    = (const float*)d_in[4];
    const float* b1    = (const float*)d_in[5];
    const float* gamma = (const float*)d_in[6];
    const float* beta  = (const float*)d_in[7];
    const float* W2    = (const float*)d_in[8];
    const float* b2    = (const float*)d_in[9];
    const float* Wlin  = (const float*)d_in[10];
    const float* blin  = (const float*)d_in[11];
    const float* negq  = (const float*)d_in[12];
    const float* posq  = (const float*)d_in[13];
    const int*   nptr  = (const int*)d_in[14];
    const int*   pptr  = (const int*)d_in[15];
    float* out = (float*)d_out;

    float*  Hq     = (float*)symp(g_Hq);
    float*  Hk     = (float*)symp(g_Hk);
    __half* midqH  = (__half*)symp(g_midqH);
    __half* midkH  = (__half*)symp(g_midkH);
    __half* HqH    = (__half*)symp(g_HqH);
    __half* HkH    = (__half*)symp(g_HkH);
    __half* W1T    = (__half*)symp(g_W1T);
    __half* WlinT  = (__half*)symp(g_WlinT);
    __half* W2T    = (__half*)symp(g_W2T);
    __half* negT   = (__half*)symp(g_negT);
    float*  scq = (float*)symp(g_scq); float* shq = (float*)symp(g_shq);
    float*  sck = (float*)symp(g_sck); float* shk = (float*)symp(g_shk);
    __half* fqH = (__half*)symp(g_featqH);
    __half* fkH = (__half*)symp(g_featkH);
    float*  fpart = (float*)symp(g_fpart);

    const int SMSZ = STAGEH * 2 * 2 * (int)sizeof(__half) / 2; // 2 stages * STAGEH halfs * 2B
    // = 2 * (2*128*72) halfs * 2 bytes = 73728
    cudaFuncSetAttribute(hgemm_k<0>, cudaFuncAttributeMaxDynamicSharedMemorySize, 73728);
    cudaFuncSetAttribute(hgemm_k<2>, cudaFuncAttributeMaxDynamicSharedMemorySize, 73728);
    cudaFuncSetAttribute(hgemm_k<3>, cudaFuncAttributeMaxDynamicSharedMemorySize, 73728);
    cudaFuncSetAttribute(hgemm_k<4>, cudaFuncAttributeMaxDynamicSharedMemorySize, 73728);
    (void)SMSZ;

    // queues copied to output (queue_update overwrites survivors)
    cudaMemcpyAsync(out + OFF_NQ2, negq, sizeof(float) * (size_t)DIM * NC,
                    cudaMemcpyDeviceToDevice);
    cudaMemcpyAsync(out + OFF_PQ2, posq, sizeof(float) * (size_t)DIM * PC,
                    cudaMemcpyDeviceToDevice);

    // ---- prep: convert activations; transpose+convert weights ----
    cvt_half_k<<<dim3(Bsz * DF / 8 / 256, 1, 2), 256>>>(
        midq, midk, midqH, midkH, Bsz * DF / 8);
    transpose_half_k<<<dim3(CC / 32, DF / 32), dim3(32, 8)>>>(Wlin, WlinT, DF, CC);
    transpose_half_k<<<dim3(DF / 32, DF / 32), dim3(32, 8)>>>(W1, W1T, DF, DF);
    transpose_half_k<<<dim3(DIM / 32, DF / 32), dim3(32, 8)>>>(W2, W2T, DF, DIM);
    transpose_half_k<<<dim3(NC / 32, DIM / 32), dim3(32, 8)>>>(negq, negT, DIM, NC);

    // ---- logits: mid @ Wlin + blin ----
    hgemm_k<0><<<dim3(CC / 128, Bsz / 128, 2), 256, 73728>>>(
        midqH, midkH, WlinT, blin, out + OFF_LQ, out + OFF_LK,
        DF, CC, nullptr, nullptr, nullptr);

    // ---- H = mid @ W1 + b1 ----
    hgemm_k<0><<<dim3(DF / 128, Bsz / 128, 2), 256, 73728>>>(
        midqH, midkH, W1T, b1, Hq, Hk, DF, DF, nullptr, nullptr, nullptr);

    // ---- BN stats + apply(relu) -> half ----
    bn_stats_k<<<dim3(DF / 32, 1, 2), dim3(32, 32)>>>(
        Hq, Hk, gamma, beta, scq, shq, sck, shk);
    bnrelu_half_k<<<dim3(Bsz * DF / 8 / 256, 1, 2), 256>>>(Hq, Hk, HqH, HkH);

    // ---- feat partials = relu(BN(H)) @ W2 (split-K 16, q/k via z) ----
    hgemm_k<2><<<dim3(1, Bsz / 128, 2 * SPLITK), 256, 73728>>>(
        HqH, HkH, W2T, nullptr, fpart, nullptr, DF, DIM,
        nullptr, nullptr, nullptr);

    // ---- reduce + bias + l2norm (fp32 + half feats) ----
    reduce_l2_k<<<dim3(Bsz, 2), DIM>>>(b2);

    // ---- sim_batch = feat_q @ feat_k^T (+ labels fused); featkH is [N][K] ----
    hgemm_k<3><<<dim3(Bsz / 128, Bsz / 128, 1), 256, 73728>>>(
        fqH, nullptr, fkH, nullptr, out + OFF_SIM, nullptr, DIM, SIMW,
        lq, lk, out + OFF_LAB);

    // ---- pos_list (+ ones) ----
    pos_k<<<Bsz, 256>>>(lq, posq, out);

    // ---- neg gathered (+ zeros into labels) ----
    hgemm_k<4><<<dim3(NC / 128, Bsz / 128, 1), 256, 73728>>>(
        fqH, nullptr, negT, nullptr, out + OFF_SIM + Bsz + PP, nullptr,
        DIM, SIMW, lq, nullptr, out + OFF_LAB + Bsz + PP);

    // ---- queue update ----
    rank_k<<<32, dim3(32, 32)>>>(lk);
    ptr_k<<<CC / 8, 256>>>(lk, nptr, pptr, out);
    queue_update_k<<<Bsz, DIM>>>(lk, nptr, pptr, out);
}

// round 13
// speedup vs baseline: 1.0788x; 1.0788x over previous
#include <cuda_runtime.h>
#include <cuda_fp16.h>
#include <cstddef>
#include <cstdint>

#define Bsz   1024
#define DF    2048
#define DIM   128
#define CC    8192
#define PP    8
#define NNq   4
#define NC    (NNq * CC)            // 32768
#define PC    (PP * CC)             // 65536
#define SIMW  (Bsz + PP + NNq * (CC - 1))  // 33796
#define SPLITK 16

static constexpr size_t OFF_SIM  = 0;
static constexpr size_t OFF_LAB  = (size_t)Bsz * SIMW;
static constexpr size_t OFF_LQ   = OFF_LAB + (size_t)Bsz * SIMW;
static constexpr size_t OFF_LK   = OFF_LQ + (size_t)Bsz * CC;
static constexpr size_t OFF_NQ2  = OFF_LK + (size_t)Bsz * CC;
static constexpr size_t OFF_PQ2  = OFF_NQ2 + (size_t)DIM * NC;
static constexpr size_t OFF_NPTR = OFF_PQ2 + (size_t)DIM * PC;
static constexpr size_t OFF_PPTR = OFF_NPTR + CC;

// ---------------- device scratch (16B-aligned for cp.async) ---------------
__device__ __align__(16) float  g_Hq[(size_t)Bsz * DF];
__device__ __align__(16) float  g_Hk[(size_t)Bsz * DF];
__device__ __align__(16) __half g_midqH[(size_t)Bsz * DF];
__device__ __align__(16) __half g_midkH[(size_t)Bsz * DF];
__device__ __align__(16) __half g_HqH[(size_t)Bsz * DF];     // relu(BN(H)) half
__device__ __align__(16) __half g_HkH[(size_t)Bsz * DF];
__device__ __align__(16) __half g_W1T[(size_t)DF * DF];      // [N][K] half
__device__ __align__(16) __half g_WlinT[(size_t)CC * DF];
__device__ __align__(16) __half g_W2T[(size_t)DIM * DF];
__device__ __align__(16) __half g_negT[(size_t)NC * DIM];
__device__ float g_scq[DF], g_shq[DF], g_sck[DF], g_shk[DF];
__device__ float g_featq[(size_t)Bsz * DIM];
__device__ float g_featk[(size_t)Bsz * DIM];
__device__ __align__(16) __half g_featqH[(size_t)Bsz * DIM];
__device__ __align__(16) __half g_featkH[(size_t)Bsz * DIM];
__device__ float g_fpart[(size_t)2 * SPLITK * Bsz * DIM];
__device__ int   g_rank[Bsz];
__device__ int   g_cntb[Bsz];

// ---------------- helpers -------------------------------------------------
__device__ __forceinline__ void mma_f16(float c[4], const unsigned a[4],
                                        const unsigned b[2]) {
    asm volatile(
        "mma.sync.aligned.m16n8k16.row.col.f32.f16.f16.f32 "
        "{%0,%1,%2,%3}, {%4,%5,%6,%7}, {%8,%9}, {%0,%1,%2,%3};"
        : "+f"(c[0]), "+f"(c[1]), "+f"(c[2]), "+f"(c[3])
        : "r"(a[0]), "r"(a[1]), "r"(a[2]), "r"(a[3]), "r"(b[0]), "r"(b[1]));
}

__device__ __forceinline__ void ldsm_x4(unsigned r[4], uint32_t addr) {
    asm volatile("ldmatrix.sync.aligned.m8n8.x4.shared.b16 {%0,%1,%2,%3}, [%4];"
                 : "=r"(r[0]), "=r"(r[1]), "=r"(r[2]), "=r"(r[3]) : "r"(addr));
}
// B stored [N][K]: mma b-frag wants stored(n=l>>2, k=2(l&3)+{0,1}) — the
// NON-trans ldmatrix mapping.
__device__ __forceinline__ void ldsm_x2(unsigned r[2], uint32_t addr) {
    asm volatile("ldmatrix.sync.aligned.m8n8.x2.shared.b16 {%0,%1}, [%2];"
                 : "=r"(r[0]), "=r"(r[1]) : "r"(addr));
}

__device__ __forceinline__ void cpa16(uint32_t saddr, const void* g) {
    asm volatile("cp.async.cg.shared.global [%0], [%1], 16;\n"
                 :: "r"(saddr), "l"(g));
}
#define CP_COMMIT() asm volatile("cp.async.commit_group;\n" ::: "memory")
#define CP_WAIT1()  asm volatile("cp.async.wait_group 1;\n" ::: "memory")

// ---------------- FP16 tensor-core GEMM, 3-stage cp.async -----------------
// 128x128 tile, BK=32 (halfs), 256 threads (8 warps, warp tile 64x32).
// A [M][K] half, Bt [N][K] half (K-major; shared staging path).
// Smem rows of 40 halfs (80B pitch): ldmatrix row banks 20r mod 32 —
// conflict-free; rows 16B-aligned. 3 stages, ONE barrier per iteration:
// buffer written at iter it (stage (it+2)%3) was last read at it-1, ordered
// by the top-of-iter barrier; same barrier publishes stage it's data.
// MODE 0: C = A@B + bias; z selects (A0,C0)/(A1,C1)
// MODE 2: split-K partial: z = qk*SPLITK + sk; C = C0 + z*Bsz*DIM
// MODE 3: plain; also writes labels_batch (lkk[n]==lqq[m]) into Lab
// MODE 4: neg scatter skipping lqq[m]'s NNq cols; writes 0.0f into Lab
#define BK    32
#define HSTR  40
#define TILEH (128 * HSTR)        // 5120 halfs per tile
#define STAGEH (2 * TILEH)        // 10240 halfs per stage (A + B)
#define SMEM_BYTES (3 * STAGEH * 2)   // 61440
template <int MODE>
__global__ __launch_bounds__(256, 2) void hgemm_k(
    const __half* __restrict__ A0, const __half* __restrict__ A1,
    const __half* __restrict__ Bt, const float* __restrict__ bias,
    float* __restrict__ C0, float* __restrict__ C1,
    int K, int ldc,
    const int* __restrict__ lqq, const int* __restrict__ lkk,
    float* __restrict__ Lab)
{
    extern __shared__ __align__(16) __half smem[];

    const int tid   = threadIdx.x;
    const int mBase = blockIdx.y * 128;
    const int nBase = blockIdx.x * 128;
    const int lane  = tid & 31;
    const int warp  = tid >> 5;
    const int g     = lane >> 2;
    const int tig   = lane & 3;
    const int wm    = (warp & 1) * 64;
    const int wn    = (warp >> 1) * 32;

    int kBeg = 0, kEnd = K;
    const __half* A;
    float* Cc;
    if (MODE == 2) {
        int qk  = blockIdx.z >> 4;
        int skc = blockIdx.z & 15;
        kBeg = skc * (K / SPLITK);
        kEnd = kBeg + K / SPLITK;
        A  = qk ? A1 : A0;
        Cc = C0 + (size_t)blockIdx.z * ((size_t)Bsz * DIM);
    } else {
        A  = blockIdx.z ? A1 : A0;
        Cc = blockIdx.z ? C1 : C0;
    }

    uint32_t sbase = (uint32_t)__cvta_generic_to_shared(smem);

    // ldmatrix per-lane address components
    const int a_row = wm + (lane & 7) + ((lane >> 3) & 1) * 8;  // + mt*16
    const int a_kof = (lane >> 4) << 3;                         // 0 or 8
    const int b_row = wn + (lane & 7);                          // + nt*8
    const int b_kof = ((lane >> 3) & 1) << 3;                   // 0 or 8

    // staging: each row = 32 halfs = 4 x 16B chunks; 2 threads/row, 2 each
    const int sr = tid >> 1;
    const int cb = (tid & 1) * 2;
    auto load_tiles = [&](int s, int kpos) {
        const __half* srcA = A  + (size_t)(mBase + sr) * K + kpos;
        const __half* srcB = Bt + (size_t)(nBase + sr) * K + kpos;
        uint32_t rowA = sbase + (uint32_t)((s * STAGEH + sr * HSTR) * 2);
        uint32_t rowB = rowA + (uint32_t)(TILEH * 2);
        #pragma unroll
        for (int i = 0; i < 2; i++) {
            int c = cb + i;
            cpa16(rowA + (uint32_t)(c * 16), srcA + c * 8);
            cpa16(rowB + (uint32_t)(c * 16), srcB + c * 8);
        }
    };

    float acc[4][4][4] = {};

    const int nIter = (kEnd - kBeg) / BK;
    load_tiles(0, kBeg);
    CP_COMMIT();
    if (nIter > 1) load_tiles(1, kBeg + BK);
    CP_COMMIT();

    for (int it = 0; it < nIter; ++it) {
        CP_WAIT1();            // stage it retired (tail groups are empty)
        __syncthreads();       // publish stage it; retire reads of (it+2)%3
        if (it + 2 < nIter) load_tiles((it + 2) % 3, kBeg + (it + 2) * BK);
        CP_COMMIT();

        const uint32_t aS = sbase + (uint32_t)((it % 3) * STAGEH * 2);
        const uint32_t bS = aS + (uint32_t)(TILEH * 2);
        #pragma unroll
        for (int kk = 0; kk < BK; kk += 16) {
            unsigned af[4][4], bf[4][2];
            #pragma unroll
            for (int mt = 0; mt < 4; mt++)
                ldsm_x4(af[mt],
                        aS + (uint32_t)(((a_row + mt * 16) * HSTR + kk + a_kof) * 2));
            #pragma unroll
            for (int nt = 0; nt < 4; nt++)
                ldsm_x2(bf[nt],
                        bS + (uint32_t)(((b_row + nt * 8) * HSTR + kk + b_kof) * 2));
            #pragma unroll
            for (int mt = 0; mt < 4; mt++)
                #pragma unroll
                for (int nt = 0; nt < 4; nt++)
                    mma_f16(acc[mt][nt], af[mt], bf[nt]);
        }
    }
    __syncthreads();

    // ---- epilogue ----
    #pragma unroll
    for (int mt = 0; mt < 4; mt++) {
        int r0 = mBase + wm + mt * 16 + g;
        int r1 = r0 + 8;
        int la0 = 0, la1 = 0, lb0 = 0, lb1 = 0;
        if (MODE == 4) { la0 = lqq[r0] * NNq; la1 = lqq[r1] * NNq; }
        if (MODE == 3) { lb0 = lqq[r0]; lb1 = lqq[r1]; }
        #pragma unroll
        for (int nt = 0; nt < 4; nt++) {
            int c = nBase + wn + nt * 8 + 2 * tig;
            const float* a4 = acc[mt][nt];
            if (MODE == 4) {
                int n0 = c, n1 = c + 1;
                if (n0 < la0) {
                    Cc [(size_t)r0 * ldc + n0] = a4[0];
                    Lab[(size_t)r0 * ldc + n0] = 0.f;
                } else if (n0 >= la0 + NNq) {
                    Cc [(size_t)r0 * ldc + n0 - NNq] = a4[0];
                    Lab[(size_t)r0 * ldc + n0 - NNq] = 0.f;
                }
                if (n1 < la0) {
                    Cc [(size_t)r0 * ldc + n1] = a4[1];
                    Lab[(size_t)r0 * ldc + n1] = 0.f;
                } else if (n1 >= la0 + NNq) {
                    Cc [(size_t)r0 * ldc + n1 - NNq] = a4[1];
                    Lab[(size_t)r0 * ldc + n1 - NNq] = 0.f;
                }
                if (n0 < la1) {
                    Cc [(size_t)r1 * ldc + n0] = a4[2];
                    Lab[(size_t)r1 * ldc + n0] = 0.f;
                } else if (n0 >= la1 + NNq) {
                    Cc [(size_t)r1 * ldc + n0 - NNq] = a4[2];
                    Lab[(size_t)r1 * ldc + n0 - NNq] = 0.f;
                }
                if (n1 < la1) {
                    Cc [(size_t)r1 * ldc + n1] = a4[3];
                    Lab[(size_t)r1 * ldc + n1] = 0.f;
                } else if (n1 >= la1 + NNq) {
                    Cc [(size_t)r1 * ldc + n1 - NNq] = a4[3];
                    Lab[(size_t)r1 * ldc + n1 - NNq] = 0.f;
                }
            } else {
                float bx = 0.f, by = 0.f;
                if (MODE == 0) { bx = bias[c]; by = bias[c + 1]; }
                float2 v0 = { a4[0] + bx, a4[1] + by };
                float2 v1 = { a4[2] + bx, a4[3] + by };
                *(float2*)(Cc + (size_t)r0 * ldc + c) = v0;
                *(float2*)(Cc + (size_t)r1 * ldc + c) = v1;
                if (MODE == 3) {
                    int k0c = lkk[c], k1c = lkk[c + 1];
                    float2 l0 = { (k0c == lb0) ? 1.f : 0.f,
                                  (k1c == lb0) ? 1.f : 0.f };
                    float2 l1 = { (k0c == lb1) ? 1.f : 0.f,
                                  (k1c == lb1) ? 1.f : 0.f };
                    *(float2*)(Lab + (size_t)r0 * ldc + c) = l0;
                    *(float2*)(Lab + (size_t)r1 * ldc + c) = l1;
                }
            }
        }
    }
}

// ---------------- prep: fp32 -> fp16 (8 / thread; q/k via z) ---------------
__global__ void cvt_half_k(const float* __restrict__ in0, const float* __restrict__ in1,
                           __half* __restrict__ o0, __half* __restrict__ o1, int n8)
{
    const float* in = blockIdx.z ? in1 : in0;
    __half* o = blockIdx.z ? o1 : o0;
    int i = blockIdx.x * blockDim.x + threadIdx.x;
    if (i >= n8) return;
    float4 a = ((const float4*)in)[i * 2];
    float4 b = ((const float4*)in)[i * 2 + 1];
    __half h[8];
    h[0] = __float2half_rn(a.x); h[1] = __float2half_rn(a.y);
    h[2] = __float2half_rn(a.z); h[3] = __float2half_rn(a.w);
    h[4] = __float2half_rn(b.x); h[5] = __float2half_rn(b.y);
    h[6] = __float2half_rn(b.z); h[7] = __float2half_rn(b.w);
    ((uint4*)o)[i] = *(const uint4*)h;
}

// ---------------- prep: transpose fp32 [R][C] -> half [C][R] ---------------
__global__ void transpose_half_k(const float* __restrict__ in, __half* __restrict__ out,
                                 int R, int C)
{
    __shared__ float t[32][33];
    int cx = blockIdx.x * 32 + threadIdx.x;
    int ry = blockIdx.y * 32 + threadIdx.y;
    #pragma unroll
    for (int j = 0; j < 32; j += 8)
        t[threadIdx.y + j][threadIdx.x] = in[(size_t)(ry + j) * C + cx];
    __syncthreads();
    int cx2 = blockIdx.y * 32 + threadIdx.x;
    int ry2 = blockIdx.x * 32 + threadIdx.y;
    #pragma unroll
    for (int j = 0; j < 32; j += 8)
        out[(size_t)(ry2 + j) * R + cx2] = __float2half_rn(t[threadIdx.x][threadIdx.y + j]);
}

// ---------------- BN stats -------------------------------------------------
__global__ void bn_stats_k(const float* __restrict__ Hq, const float* __restrict__ Hk,
                           const float* __restrict__ gamma, const float* __restrict__ beta,
                           float* __restrict__ scq, float* __restrict__ shq,
                           float* __restrict__ sck, float* __restrict__ shk)
{
    const float* H = blockIdx.z ? Hk : Hq;
    float* scale = blockIdx.z ? sck : scq;
    float* shift = blockIdx.z ? shk : shq;
    int f = blockIdx.x * 32 + threadIdx.x;
    float s = 0.f, ss = 0.f;
    for (int r = threadIdx.y; r < Bsz; r += 32) {
        float v = H[(size_t)r * DF + f];
        s += v; ss += v * v;
    }
    __shared__ float sh_s[32][33], sh_ss[32][33];
    sh_s[threadIdx.y][threadIdx.x]  = s;
    sh_ss[threadIdx.y][threadIdx.x] = ss;
    __syncthreads();
    if (threadIdx.y == 0) {
        #pragma unroll
        for (int y = 1; y < 32; y++) {
            s += sh_s[y][threadIdx.x]; ss += sh_ss[y][threadIdx.x];
        }
        float mu  = s * (1.f / Bsz);
        float var = ss * (1.f / Bsz) - mu * mu;
        float rst = rsqrtf(var + 1e-5f);
        float scv = rst * gamma[f];
        scale[f] = scv;
        shift[f] = beta[f] - mu * scv;
    }
}

// ---------------- BN apply + relu -> half ----------------------------------
__global__ void bnrelu_half_k(const float* __restrict__ Hq, const float* __restrict__ Hk,
                              __half* __restrict__ Rq, __half* __restrict__ Rk)
{
    const float* H = blockIdx.z ? Hk : Hq;
    __half* R = blockIdx.z ? Rk : Rq;
    const float* sc = blockIdx.z ? g_sck : g_scq;
    const float* sh = blockIdx.z ? g_shk : g_shq;
    int i = blockIdx.x * blockDim.x + threadIdx.x;   // 8-float group
    int f = (i * 8) & (DF - 1);
    float4 a = ((const float4*)H)[i * 2];
    float4 b = ((const float4*)H)[i * 2 + 1];
    float4 sa = *(const float4*)(sc + f);
    float4 sb = *(const float4*)(sc + f + 4);
    float4 ha = *(const float4*)(sh + f);
    float4 hb = *(const float4*)(sh + f + 4);
    __half h[8];
    h[0] = __float2half_rn(fmaxf(fmaf(a.x, sa.x, ha.x), 0.f));
    h[1] = __float2half_rn(fmaxf(fmaf(a.y, sa.y, ha.y), 0.f));
    h[2] = __float2half_rn(fmaxf(fmaf(a.z, sa.z, ha.z), 0.f));
    h[3] = __float2half_rn(fmaxf(fmaf(a.w, sa.w, ha.w), 0.f));
    h[4] = __float2half_rn(fmaxf(fmaf(b.x, sb.x, hb.x), 0.f));
    h[5] = __float2half_rn(fmaxf(fmaf(b.y, sb.y, hb.y), 0.f));
    h[6] = __float2half_rn(fmaxf(fmaf(b.z, sb.z, hb.z), 0.f));
    h[7] = __float2half_rn(fmaxf(fmaf(b.w, sb.w, hb.w), 0.f));
    ((uint4*)R)[i] = *(const uint4*)h;
}

// ---------------- split-K reduce + bias + l2norm ---------------------------
__global__ void reduce_l2_k(const float* __restrict__ b2)
{
    int qk = blockIdx.y, b = blockIdx.x, d = threadIdx.x;  // d: 0..127
    const float* part = g_fpart + (size_t)qk * SPLITK * Bsz * DIM;
    float v = b2[d];
    #pragma unroll
    for (int s = 0; s < SPLITK; s++)
        v += part[(size_t)s * Bsz * DIM + (size_t)b * DIM + d];
    float ss = v * v;
    #pragma unroll
    for (int o = 16; o; o >>= 1) ss += __shfl_xor_sync(0xffffffffu, ss, o);
    __shared__ float ws[4];
    if ((d & 31) == 0) ws[d >> 5] = ss;
    __syncthreads();
    ss = ws[0] + ws[1] + ws[2] + ws[3];
    float inv = 1.f / fmaxf(sqrtf(ss), 1e-12f);
    float vn = v * inv;
    if (qk) {
        g_featk[(size_t)b * DIM + d] = vn;
        g_featkH[(size_t)b * DIM + d] = __float2half_rn(vn);
    } else {
        g_featq[(size_t)b * DIM + d] = vn;
        g_featqH[(size_t)b * DIM + d] = __float2half_rn(vn);
    }
}

// ---------------- pos_list (+ ones into labels) ----------------------------
__global__ void pos_k(const int* __restrict__ lq, const float* __restrict__ posq,
                      float* __restrict__ out)
{
    int b = blockIdx.x, tid = threadIdx.x;
    __shared__ float fr[DIM];
    if (tid < DIM) fr[tid] = g_featq[(size_t)b * DIM + tid];
    __syncthreads();
    int w = tid >> 5, lane = tid & 31;
    int col = lq[b] * PP + w;
    float s = 0.f;
    for (int d = lane; d < DIM; d += 32)
        s += fr[d] * posq[(size_t)d * PC + col];
    #pragma unroll
    for (int o = 16; o; o >>= 1) s += __shfl_down_sync(0xffffffffu, s, o);
    if (lane == 0) {
        out[OFF_SIM + (size_t)b * SIMW + Bsz + w] = s;
        out[OFF_LAB + (size_t)b * SIMW + Bsz + w] = 1.f;
    }
}

// ---------------- occurrence rank + count (warp-per-row) -------------------
__global__ void rank_k(const int* __restrict__ lk)
{
    __shared__ int sl[Bsz];
    int t = threadIdx.y * 32 + threadIdx.x;
    for (int i = t; i < Bsz; i += 1024) sl[i] = lk[i];
    __syncthreads();
    int b = blockIdx.x * 32 + threadIdx.y;
    int lab = sl[b];
    int r = 0, c = 0;
    for (int j = threadIdx.x; j < Bsz; j += 32) {
        int e = (sl[j] == lab);
        c += e;
        r += e & (j < b);
    }
    #pragma unroll
    for (int o = 16; o; o >>= 1) {
        c += __shfl_down_sync(0xffffffffu, c, o);
        r += __shfl_down_sync(0xffffffffu, r, o);
    }
    if (threadIdx.x == 0) { g_rank[b] = r; g_cntb[b] = c; }
}

// ---------------- ptr outputs (warp-per-class) -----------------------------
__global__ void ptr_k(const int* __restrict__ lk, const int* __restrict__ nptr,
                      const int* __restrict__ pptr, float* __restrict__ out)
{
    __shared__ int sl[Bsz];
    for (int i = threadIdx.x; i < Bsz; i += 256) sl[i] = lk[i];
    __syncthreads();
    int w = threadIdx.x >> 5, lane = threadIdx.x & 31;
    int c = blockIdx.x * 8 + w;
    int cnt = 0;
    for (int j = lane; j < Bsz; j += 32) cnt += (sl[j] == c);
    #pragma unroll
    for (int o = 16; o; o >>= 1) cnt += __shfl_down_sync(0xffffffffu, cnt, o);
    if (lane == 0) {
        out[OFF_NPTR + c] = (float)((nptr[c] + cnt) % NNq);
        out[OFF_PPTR + c] = (float)((pptr[c] + cnt) % PP);
    }
}

// ---------------- queue overwrite ------------------------------------------
__global__ void queue_update_k(const int* __restrict__ lk, const int* __restrict__ nptr,
                               const int* __restrict__ pptr, float* __restrict__ out)
{
    int b = blockIdx.x;
    int d = threadIdx.x;   // 128
    int lab = lk[b];
    int r = g_rank[b];
    int c = g_cntb[b];
    float v = g_featk[(size_t)b * DIM + d];
    if (r >= c - NNq) {
        int slot = (nptr[lab] + r) % NNq;
        out[OFF_NQ2 + (size_t)d * NC + lab * NNq + slot] = v;
    }
    if (r >= c - PP) {
        int slot = (pptr[lab] + r) % PP;
        out[OFF_PQ2 + (size_t)d * PC + lab * PP + slot] = v;
    }
}

// ---------------- host launcher --------------------------------------------
static void* symp(const void* sym) {
    void* p = nullptr;
    cudaGetSymbolAddress(&p, sym);
    return p;
}

extern "C" void kernel_launch(void* const* d_in, const int* in_sizes, int n_in,
                              void* d_out, int out_size)
{
    (void)in_sizes; (void)n_in; (void)out_size;
    const float* midq  = (const float*)d_in[0];
    const float* midk  = (const float*)d_in[1];
    const int*   lq    = (const int*)d_in[2];
    const int*   lk    = (const int*)d_in[3];
    const float* W1    = (const float*)d_in[4];
    const float* b1    = (const float*)d_in[5];
    const float* gamma = (const float*)d_in[6];
    const float* beta  = (const float*)d_in[7];
    const float* W2    = (const float*)d_in[8];
    const float* b2    = (const float*)d_in[9];
    const float* Wlin  = (const float*)d_in[10];
    const float* blin  = (const float*)d_in[11];
    const float* negq  = (const float*)d_in[12];
    const float* posq  = (const float*)d_in[13];
    const int*   nptr  = (const int*)d_in[14];
    const int*   pptr  = (const int*)d_in[15];
    float* out = (float*)d_out;

    float*  Hq     = (float*)symp(g_Hq);
    float*  Hk     = (float*)symp(g_Hk);
    __half* midqH  = (__half*)symp(g_midqH);
    __half* midkH  = (__half*)symp(g_midkH);
    __half* HqH    = (__half*)symp(g_HqH);
    __half* HkH    = (__half*)symp(g_HkH);
    __half* W1T    = (__half*)symp(g_W1T);
    __half* WlinT  = (__half*)symp(g_WlinT);
    __half* W2T    = (__half*)symp(g_W2T);
    __half* negT   = (__half*)symp(g_negT);
    float*  scq = (float*)symp(g_scq); float* shq = (float*)symp(g_shq);
    float*  sck = (float*)symp(g_sck); float* shk = (float*)symp(g_shk);
    __half* fqH = (__half*)symp(g_featqH);
    __half* fkH = (__half*)symp(g_featkH);
    float*  fpart = (float*)symp(g_fpart);

    cudaFuncSetAttribute(hgemm_k<0>, cudaFuncAttributeMaxDynamicSharedMemorySize, SMEM_BYTES);
    cudaFuncSetAttribute(hgemm_k<2>, cudaFuncAttributeMaxDynamicSharedMemorySize, SMEM_BYTES);
    cudaFuncSetAttribute(hgemm_k<3>, cudaFuncAttributeMaxDynamicSharedMemorySize, SMEM_BYTES);
    cudaFuncSetAttribute(hgemm_k<4>, cudaFuncAttributeMaxDynamicSharedMemorySize, SMEM_BYTES);

    // queues copied to output (queue_update overwrites survivors)
    cudaMemcpyAsync(out + OFF_NQ2, negq, sizeof(float) * (size_t)DIM * NC,
                    cudaMemcpyDeviceToDevice);
    cudaMemcpyAsync(out + OFF_PQ2, posq, sizeof(float) * (size_t)DIM * PC,
                    cudaMemcpyDeviceToDevice);

    // ---- prep: convert activations; transpose+convert weights ----
    cvt_half_k<<<dim3(Bsz * DF / 8 / 256, 1, 2), 256>>>(
        midq, midk, midqH, midkH, Bsz * DF / 8);
    transpose_half_k<<<dim3(CC / 32, DF / 32), dim3(32, 8)>>>(Wlin, WlinT, DF, CC);
    transpose_half_k<<<dim3(DF / 32, DF / 32), dim3(32, 8)>>>(W1, W1T, DF, DF);
    transpose_half_k<<<dim3(DIM / 32, DF / 32), dim3(32, 8)>>>(W2, W2T, DF, DIM);
    transpose_half_k<<<dim3(NC / 32, DIM / 32), dim3(32, 8)>>>(negq, negT, DIM, NC);

    // ---- logits: mid @ Wlin + blin ----
    hgemm_k<0><<<dim3(CC / 128, Bsz / 128, 2), 256, SMEM_BYTES>>>(
        midqH, midkH, WlinT, blin, out + OFF_LQ, out + OFF_LK,
        DF, CC, nullptr, nullptr, nullptr);

    // ---- H = mid @ W1 + b1 ----
    hgemm_k<0><<<dim3(DF / 128, Bsz / 128, 2), 256, SMEM_BYTES>>>(
        midqH, midkH, W1T, b1, Hq, Hk, DF, DF, nullptr, nullptr, nullptr);

    // ---- BN stats + apply(relu) -> half ----
    bn_stats_k<<<dim3(DF / 32, 1, 2), dim3(32, 32)>>>(
        Hq, Hk, gamma, beta, scq, shq, sck, shk);
    bnrelu_half_k<<<dim3(Bsz * DF / 8 / 256, 1, 2), 256>>>(Hq, Hk, HqH, HkH);

    // ---- feat partials = relu(BN(H)) @ W2 (split-K 16, q/k via z) ----
    hgemm_k<2><<<dim3(1, Bsz / 128, 2 * SPLITK), 256, SMEM_BYTES>>>(
        HqH, HkH, W2T, nullptr, fpart, nullptr, DF, DIM,
        nullptr, nullptr, nullptr);

    // ---- reduce + bias + l2norm (fp32 + half feats) ----
    reduce_l2_k<<<dim3(Bsz, 2), DIM>>>(b2);

    // ---- sim_batch = feat_q @ feat_k^T (+ labels fused); featkH is [N][K] ----
    hgemm_k<3><<<dim3(Bsz / 128, Bsz / 128, 1), 256, SMEM_BYTES>>>(
        fqH, nullptr, fkH, nullptr, out + OFF_SIM, nullptr, DIM, SIMW,
        lq, lk, out + OFF_LAB);

    // ---- pos_list (+ ones) ----
    pos_k<<<Bsz, 256>>>(lq, posq, out);

    // ---- neg gathered (+ zeros into labels) ----
    hgemm_k<4><<<dim3(NC / 128, Bsz / 128, 1), 256, SMEM_BYTES>>>(
        fqH, nullptr, negT, nullptr, out + OFF_SIM + Bsz + PP, nullptr,
        DIM, SIMW, lq, nullptr, out + OFF_LAB + Bsz + PP);

    // ---- queue update ----
    rank_k<<<32, dim3(32, 32)>>>(lk);
    ptr_k<<<CC / 8, 256>>>(lk, nptr, pptr, out);
    queue_update_k<<<Bsz, DIM>>>(lk, nptr, pptr, out);
}

// round 14
// speedup vs baseline: 1.1057x; 1.0250x over previous
#include <cuda_runtime.h>
#include <cuda_fp16.h>
#include <cstddef>
#include <cstdint>

#define Bsz   1024
#define DF    2048
#define DIM   128
#define CC    8192
#define PP    8
#define NNq   4
#define NC    (NNq * CC)            // 32768
#define PC    (PP * CC)             // 65536
#define SIMW  (Bsz + PP + NNq * (CC - 1))  // 33796
#define SPLITK 16

static constexpr size_t OFF_SIM  = 0;
static constexpr size_t OFF_LAB  = (size_t)Bsz * SIMW;
static constexpr size_t OFF_LQ   = OFF_LAB + (size_t)Bsz * SIMW;
static constexpr size_t OFF_LK   = OFF_LQ + (size_t)Bsz * CC;
static constexpr size_t OFF_NQ2  = OFF_LK + (size_t)Bsz * CC;
static constexpr size_t OFF_PQ2  = OFF_NQ2 + (size_t)DIM * NC;
static constexpr size_t OFF_NPTR = OFF_PQ2 + (size_t)DIM * PC;
static constexpr size_t OFF_PPTR = OFF_NPTR + CC;

// ---------------- device scratch (16B-aligned for cp.async) ---------------
__device__ __align__(16) float  g_Hq[(size_t)Bsz * DF];
__device__ __align__(16) float  g_Hk[(size_t)Bsz * DF];
__device__ __align__(16) __half g_midqH[(size_t)Bsz * DF];
__device__ __align__(16) __half g_midkH[(size_t)Bsz * DF];
__device__ __align__(16) __half g_HqH[(size_t)Bsz * DF];     // relu(BN(H)) half
__device__ __align__(16) __half g_HkH[(size_t)Bsz * DF];
__device__ __align__(16) __half g_W1T[(size_t)DF * DF];      // [N][K] half
__device__ __align__(16) __half g_WlinT[(size_t)CC * DF];
__device__ __align__(16) __half g_W2T[(size_t)DIM * DF];
__device__ __align__(16) __half g_negT[(size_t)NC * DIM];
__device__ float g_scq[DF], g_shq[DF], g_sck[DF], g_shk[DF];
__device__ float g_featq[(size_t)Bsz * DIM];
__device__ float g_featk[(size_t)Bsz * DIM];
__device__ __align__(16) __half g_featqH[(size_t)Bsz * DIM];
__device__ __align__(16) __half g_featkH[(size_t)Bsz * DIM];
__device__ float g_fpart[(size_t)2 * SPLITK * Bsz * DIM];
__device__ int   g_rank[Bsz];
__device__ int   g_cntb[Bsz];

// ---------------- helpers -------------------------------------------------
__device__ __forceinline__ void mma_f16(float c[4], const unsigned a[4],
                                        const unsigned b[2]) {
    asm volatile(
        "mma.sync.aligned.m16n8k16.row.col.f32.f16.f16.f32 "
        "{%0,%1,%2,%3}, {%4,%5,%6,%7}, {%8,%9}, {%0,%1,%2,%3};"
        : "+f"(c[0]), "+f"(c[1]), "+f"(c[2]), "+f"(c[3])
        : "r"(a[0]), "r"(a[1]), "r"(a[2]), "r"(a[3]), "r"(b[0]), "r"(b[1]));
}

__device__ __forceinline__ void ldsm_x4(unsigned r[4], uint32_t addr) {
    asm volatile("ldmatrix.sync.aligned.m8n8.x4.shared.b16 {%0,%1,%2,%3}, [%4];"
                 : "=r"(r[0]), "=r"(r[1]), "=r"(r[2]), "=r"(r[3]) : "r"(addr));
}
// B stored [N][K]: mma b-frag wants stored(n=l>>2, k=2(l&3)+{0,1}) — the
// NON-trans ldmatrix mapping.
__device__ __forceinline__ void ldsm_x2(unsigned r[2], uint32_t addr) {
    asm volatile("ldmatrix.sync.aligned.m8n8.x2.shared.b16 {%0,%1}, [%2];"
                 : "=r"(r[0]), "=r"(r[1]) : "r"(addr));
}

__device__ __forceinline__ void cpa16(uint32_t saddr, const void* g) {
    asm volatile("cp.async.cg.shared.global [%0], [%1], 16;\n"
                 :: "r"(saddr), "l"(g));
}
#define CP_COMMIT() asm volatile("cp.async.commit_group;\n" ::: "memory")
#define CP_WAIT1()  asm volatile("cp.async.wait_group 1;\n" ::: "memory")

// ---------------- FP16 tensor-core GEMM, 3-stage cp.async -----------------
// (identical to the 615us champion)
#define BK    32
#define HSTR  40
#define TILEH (128 * HSTR)        // 5120 halfs per tile
#define STAGEH (2 * TILEH)        // 10240 halfs per stage (A + B)
#define SMEM_BYTES (3 * STAGEH * 2)   // 61440
template <int MODE>
__global__ __launch_bounds__(256, 2) void hgemm_k(
    const __half* __restrict__ A0, const __half* __restrict__ A1,
    const __half* __restrict__ Bt, const float* __restrict__ bias,
    float* __restrict__ C0, float* __restrict__ C1,
    int K, int ldc,
    const int* __restrict__ lqq, const int* __restrict__ lkk,
    float* __restrict__ Lab)
{
    extern __shared__ __align__(16) __half smem[];

    const int tid   = threadIdx.x;
    const int mBase = blockIdx.y * 128;
    const int nBase = blockIdx.x * 128;
    const int lane  = tid & 31;
    const int warp  = tid >> 5;
    const int g     = lane >> 2;
    const int tig   = lane & 3;
    const int wm    = (warp & 1) * 64;
    const int wn    = (warp >> 1) * 32;

    int kBeg = 0, kEnd = K;
    const __half* A;
    float* Cc;
    if (MODE == 2) {
        int qk  = blockIdx.z >> 4;
        int skc = blockIdx.z & 15;
        kBeg = skc * (K / SPLITK);
        kEnd = kBeg + K / SPLITK;
        A  = qk ? A1 : A0;
        Cc = C0 + (size_t)blockIdx.z * ((size_t)Bsz * DIM);
    } else {
        A  = blockIdx.z ? A1 : A0;
        Cc = blockIdx.z ? C1 : C0;
    }

    uint32_t sbase = (uint32_t)__cvta_generic_to_shared(smem);

    // ldmatrix per-lane address components
    const int a_row = wm + (lane & 7) + ((lane >> 3) & 1) * 8;  // + mt*16
    const int a_kof = (lane >> 4) << 3;                         // 0 or 8
    const int b_row = wn + (lane & 7);                          // + nt*8
    const int b_kof = ((lane >> 3) & 1) << 3;                   // 0 or 8

    // staging: each row = 32 halfs = 4 x 16B chunks; 2 threads/row, 2 each
    const int sr = tid >> 1;
    const int cb = (tid & 1) * 2;
    auto load_tiles = [&](int s, int kpos) {
        const __half* srcA = A  + (size_t)(mBase + sr) * K + kpos;
        const __half* srcB = Bt + (size_t)(nBase + sr) * K + kpos;
        uint32_t rowA = sbase + (uint32_t)((s * STAGEH + sr * HSTR) * 2);
        uint32_t rowB = rowA + (uint32_t)(TILEH * 2);
        #pragma unroll
        for (int i = 0; i < 2; i++) {
            int c = cb + i;
            cpa16(rowA + (uint32_t)(c * 16), srcA + c * 8);
            cpa16(rowB + (uint32_t)(c * 16), srcB + c * 8);
        }
    };

    float acc[4][4][4] = {};

    const int nIter = (kEnd - kBeg) / BK;
    load_tiles(0, kBeg);
    CP_COMMIT();
    if (nIter > 1) load_tiles(1, kBeg + BK);
    CP_COMMIT();

    for (int it = 0; it < nIter; ++it) {
        CP_WAIT1();            // stage it retired (tail groups are empty)
        __syncthreads();       // publish stage it; retire reads of (it+2)%3
        if (it + 2 < nIter) load_tiles((it + 2) % 3, kBeg + (it + 2) * BK);
        CP_COMMIT();

        const uint32_t aS = sbase + (uint32_t)((it % 3) * STAGEH * 2);
        const uint32_t bS = aS + (uint32_t)(TILEH * 2);
        #pragma unroll
        for (int kk = 0; kk < BK; kk += 16) {
            unsigned af[4][4], bf[4][2];
            #pragma unroll
            for (int mt = 0; mt < 4; mt++)
                ldsm_x4(af[mt],
                        aS + (uint32_t)(((a_row + mt * 16) * HSTR + kk + a_kof) * 2));
            #pragma unroll
            for (int nt = 0; nt < 4; nt++)
                ldsm_x2(bf[nt],
                        bS + (uint32_t)(((b_row + nt * 8) * HSTR + kk + b_kof) * 2));
            #pragma unroll
            for (int mt = 0; mt < 4; mt++)
                #pragma unroll
                for (int nt = 0; nt < 4; nt++)
                    mma_f16(acc[mt][nt], af[mt], bf[nt]);
        }
    }
    __syncthreads();

    // ---- epilogue ----
    #pragma unroll
    for (int mt = 0; mt < 4; mt++) {
        int r0 = mBase + wm + mt * 16 + g;
        int r1 = r0 + 8;
        int la0 = 0, la1 = 0, lb0 = 0, lb1 = 0;
        if (MODE == 4) { la0 = lqq[r0] * NNq; la1 = lqq[r1] * NNq; }
        if (MODE == 3) { lb0 = lqq[r0]; lb1 = lqq[r1]; }
        #pragma unroll
        for (int nt = 0; nt < 4; nt++) {
            int c = nBase + wn + nt * 8 + 2 * tig;
            const float* a4 = acc[mt][nt];
            if (MODE == 4) {
                int n0 = c, n1 = c + 1;
                if (n0 < la0) {
                    Cc [(size_t)r0 * ldc + n0] = a4[0];
                    Lab[(size_t)r0 * ldc + n0] = 0.f;
                } else if (n0 >= la0 + NNq) {
                    Cc [(size_t)r0 * ldc + n0 - NNq] = a4[0];
                    Lab[(size_t)r0 * ldc + n0 - NNq] = 0.f;
                }
                if (n1 < la0) {
                    Cc [(size_t)r0 * ldc + n1] = a4[1];
                    Lab[(size_t)r0 * ldc + n1] = 0.f;
                } else if (n1 >= la0 + NNq) {
                    Cc [(size_t)r0 * ldc + n1 - NNq] = a4[1];
                    Lab[(size_t)r0 * ldc + n1 - NNq] = 0.f;
                }
                if (n0 < la1) {
                    Cc [(size_t)r1 * ldc + n0] = a4[2];
                    Lab[(size_t)r1 * ldc + n0] = 0.f;
                } else if (n0 >= la1 + NNq) {
                    Cc [(size_t)r1 * ldc + n0 - NNq] = a4[2];
                    Lab[(size_t)r1 * ldc + n0 - NNq] = 0.f;
                }
                if (n1 < la1) {
                    Cc [(size_t)r1 * ldc + n1] = a4[3];
                    Lab[(size_t)r1 * ldc + n1] = 0.f;
                } else if (n1 >= la1 + NNq) {
                    Cc [(size_t)r1 * ldc + n1 - NNq] = a4[3];
                    Lab[(size_t)r1 * ldc + n1 - NNq] = 0.f;
                }
            } else {
                float bx = 0.f, by = 0.f;
                if (MODE == 0) { bx = bias[c]; by = bias[c + 1]; }
                float2 v0 = { a4[0] + bx, a4[1] + by };
                float2 v1 = { a4[2] + bx, a4[3] + by };
                *(float2*)(Cc + (size_t)r0 * ldc + c) = v0;
                *(float2*)(Cc + (size_t)r1 * ldc + c) = v1;
                if (MODE == 3) {
                    int k0c = lkk[c], k1c = lkk[c + 1];
                    float2 l0 = { (k0c == lb0) ? 1.f : 0.f,
                                  (k1c == lb0) ? 1.f : 0.f };
                    float2 l1 = { (k0c == lb1) ? 1.f : 0.f,
                                  (k1c == lb1) ? 1.f : 0.f };
                    *(float2*)(Lab + (size_t)r0 * ldc + c) = l0;
                    *(float2*)(Lab + (size_t)r1 * ldc + c) = l1;
                }
            }
        }
    }
}

// ---------------- prep: fp32 -> fp16 (8 / thread; q/k via z) ---------------
__global__ void cvt_half_k(const float* __restrict__ in0, const float* __restrict__ in1,
                           __half* __restrict__ o0, __half* __restrict__ o1, int n8)
{
    const float* in = blockIdx.z ? in1 : in0;
    __half* o = blockIdx.z ? o1 : o0;
    int i = blockIdx.x * blockDim.x + threadIdx.x;
    if (i >= n8) return;
    float4 a = ((const float4*)in)[i * 2];
    float4 b = ((const float4*)in)[i * 2 + 1];
    __half h[8];
    h[0] = __float2half_rn(a.x); h[1] = __float2half_rn(a.y);
    h[2] = __float2half_rn(a.z); h[3] = __float2half_rn(a.w);
    h[4] = __float2half_rn(b.x); h[5] = __float2half_rn(b.y);
    h[6] = __float2half_rn(b.z); h[7] = __float2half_rn(b.w);
    ((uint4*)o)[i] = *(const uint4*)h;
}

// ---------------- prep: transpose fp32 [R][C] -> half [C][R] ---------------
__global__ void transpose_half_k(const float* __restrict__ in, __half* __restrict__ out,
                                 int R, int C)
{
    __shared__ float t[32][33];
    int cx = blockIdx.x * 32 + threadIdx.x;
    int ry = blockIdx.y * 32 + threadIdx.y;
    #pragma unroll
    for (int j = 0; j < 32; j += 8)
        t[threadIdx.y + j][threadIdx.x] = in[(size_t)(ry + j) * C + cx];
    __syncthreads();
    int cx2 = blockIdx.y * 32 + threadIdx.x;
    int ry2 = blockIdx.x * 32 + threadIdx.y;
    #pragma unroll
    for (int j = 0; j < 32; j += 8)
        out[(size_t)(ry2 + j) * R + cx2] = __float2half_rn(t[threadIdx.x][threadIdx.y + j]);
}

// ---------------- BN stats -------------------------------------------------
__global__ void bn_stats_k(const float* __restrict__ Hq, const float* __restrict__ Hk,
                           const float* __restrict__ gamma, const float* __restrict__ beta,
                           float* __restrict__ scq, float* __restrict__ shq,
                           float* __restrict__ sck, float* __restrict__ shk)
{
    const float* H = blockIdx.z ? Hk : Hq;
    float* scale = blockIdx.z ? sck : scq;
    float* shift = blockIdx.z ? shk : shq;
    int f = blockIdx.x * 32 + threadIdx.x;
    float s = 0.f, ss = 0.f;
    for (int r = threadIdx.y; r < Bsz; r += 32) {
        float v = H[(size_t)r * DF + f];
        s += v; ss += v * v;
    }
    __shared__ float sh_s[32][33], sh_ss[32][33];
    sh_s[threadIdx.y][threadIdx.x]  = s;
    sh_ss[threadIdx.y][threadIdx.x] = ss;
    __syncthreads();
    if (threadIdx.y == 0) {
        #pragma unroll
        for (int y = 1; y < 32; y++) {
            s += sh_s[y][threadIdx.x]; ss += sh_ss[y][threadIdx.x];
        }
        float mu  = s * (1.f / Bsz);
        float var = ss * (1.f / Bsz) - mu * mu;
        float rst = rsqrtf(var + 1e-5f);
        float scv = rst * gamma[f];
        scale[f] = scv;
        shift[f] = beta[f] - mu * scv;
    }
}

// ---------------- BN apply + relu -> half ----------------------------------
__global__ void bnrelu_half_k(const float* __restrict__ Hq, const float* __restrict__ Hk,
                              __half* __restrict__ Rq, __half* __restrict__ Rk)
{
    const float* H = blockIdx.z ? Hk : Hq;
    __half* R = blockIdx.z ? Rk : Rq;
    const float* sc = blockIdx.z ? g_sck : g_scq;
    const float* sh = blockIdx.z ? g_shk : g_shq;
    int i = blockIdx.x * blockDim.x + threadIdx.x;   // 8-float group
    int f = (i * 8) & (DF - 1);
    float4 a = ((const float4*)H)[i * 2];
    float4 b = ((const float4*)H)[i * 2 + 1];
    float4 sa = *(const float4*)(sc + f);
    float4 sb = *(const float4*)(sc + f + 4);
    float4 ha = *(const float4*)(sh + f);
    float4 hb = *(const float4*)(sh + f + 4);
    __half h[8];
    h[0] = __float2half_rn(fmaxf(fmaf(a.x, sa.x, ha.x), 0.f));
    h[1] = __float2half_rn(fmaxf(fmaf(a.y, sa.y, ha.y), 0.f));
    h[2] = __float2half_rn(fmaxf(fmaf(a.z, sa.z, ha.z), 0.f));
    h[3] = __float2half_rn(fmaxf(fmaf(a.w, sa.w, ha.w), 0.f));
    h[4] = __float2half_rn(fmaxf(fmaf(b.x, sb.x, hb.x), 0.f));
    h[5] = __float2half_rn(fmaxf(fmaf(b.y, sb.y, hb.y), 0.f));
    h[6] = __float2half_rn(fmaxf(fmaf(b.z, sb.z, hb.z), 0.f));
    h[7] = __float2half_rn(fmaxf(fmaf(b.w, sb.w, hb.w), 0.f));
    ((uint4*)R)[i] = *(const uint4*)h;
}

// ---------------- split-K reduce + bias + l2norm ---------------------------
__global__ void reduce_l2_k(const float* __restrict__ b2)
{
    int qk = blockIdx.y, b = blockIdx.x, d = threadIdx.x;  // d: 0..127
    const float* part = g_fpart + (size_t)qk * SPLITK * Bsz * DIM;
    float v = b2[d];
    #pragma unroll
    for (int s = 0; s < SPLITK; s++)
        v += part[(size_t)s * Bsz * DIM + (size_t)b * DIM + d];
    float ss = v * v;
    #pragma unroll
    for (int o = 16; o; o >>= 1) ss += __shfl_xor_sync(0xffffffffu, ss, o);
    __shared__ float ws[4];
    if ((d & 31) == 0) ws[d >> 5] = ss;
    __syncthreads();
    ss = ws[0] + ws[1] + ws[2] + ws[3];
    float inv = 1.f / fmaxf(sqrtf(ss), 1e-12f);
    float vn = v * inv;
    if (qk) {
        g_featk[(size_t)b * DIM + d] = vn;
        g_featkH[(size_t)b * DIM + d] = __float2half_rn(vn);
    } else {
        g_featq[(size_t)b * DIM + d] = vn;
        g_featqH[(size_t)b * DIM + d] = __float2half_rn(vn);
    }
}

// ---------------- pos_list (+ ones into labels) ----------------------------
__global__ void pos_k(const int* __restrict__ lq, const float* __restrict__ posq,
                      float* __restrict__ out)
{
    int b = blockIdx.x, tid = threadIdx.x;
    __shared__ float fr[DIM];
    if (tid < DIM) fr[tid] = g_featq[(size_t)b * DIM + tid];
    __syncthreads();
    int w = tid >> 5, lane = tid & 31;
    int col = lq[b] * PP + w;
    float s = 0.f;
    for (int d = lane; d < DIM; d += 32)
        s += fr[d] * posq[(size_t)d * PC + col];
    #pragma unroll
    for (int o = 16; o; o >>= 1) s += __shfl_down_sync(0xffffffffu, s, o);
    if (lane == 0) {
        out[OFF_SIM + (size_t)b * SIMW + Bsz + w] = s;
        out[OFF_LAB + (size_t)b * SIMW + Bsz + w] = 1.f;
    }
}

// ---------------- occurrence rank + count (warp-per-row) -------------------
__global__ void rank_k(const int* __restrict__ lk)
{
    __shared__ int sl[Bsz];
    int t = threadIdx.y * 32 + threadIdx.x;
    for (int i = t; i < Bsz; i += 1024) sl[i] = lk[i];
    __syncthreads();
    int b = blockIdx.x * 32 + threadIdx.y;
    int lab = sl[b];
    int r = 0, c = 0;
    for (int j = threadIdx.x; j < Bsz; j += 32) {
        int e = (sl[j] == lab);
        c += e;
        r += e & (j < b);
    }
    #pragma unroll
    for (int o = 16; o; o >>= 1) {
        c += __shfl_down_sync(0xffffffffu, c, o);
        r += __shfl_down_sync(0xffffffffu, r, o);
    }
    if (threadIdx.x == 0) { g_rank[b] = r; g_cntb[b] = c; }
}

// ---------------- ptr outputs (warp-per-class) -----------------------------
__global__ void ptr_k(const int* __restrict__ lk, const int* __restrict__ nptr,
                      const int* __restrict__ pptr, float* __restrict__ out)
{
    __shared__ int sl[Bsz];
    for (int i = threadIdx.x; i < Bsz; i += 256) sl[i] = lk[i];
    __syncthreads();
    int w = threadIdx.x >> 5, lane = threadIdx.x & 31;
    int c = blockIdx.x * 8 + w;
    int cnt = 0;
    for (int j = lane; j < Bsz; j += 32) cnt += (sl[j] == c);
    #pragma unroll
    for (int o = 16; o; o >>= 1) cnt += __shfl_down_sync(0xffffffffu, cnt, o);
    if (lane == 0) {
        out[OFF_NPTR + c] = (float)((nptr[c] + cnt) % NNq);
        out[OFF_PPTR + c] = (float)((pptr[c] + cnt) % PP);
    }
}

// ---------------- queue overwrite ------------------------------------------
__global__ void queue_update_k(const int* __restrict__ lk, const int* __restrict__ nptr,
                               const int* __restrict__ pptr, float* __restrict__ out)
{
    int b = blockIdx.x;
    int d = threadIdx.x;   // 128
    int lab = lk[b];
    int r = g_rank[b];
    int c = g_cntb[b];
    float v = g_featk[(size_t)b * DIM + d];
    if (r >= c - NNq) {
        int slot = (nptr[lab] + r) % NNq;
        out[OFF_NQ2 + (size_t)d * NC + lab * NNq + slot] = v;
    }
    if (r >= c - PP) {
        int slot = (pptr[lab] + r) % PP;
        out[OFF_PQ2 + (size_t)d * PC + lab * PP + slot] = v;
    }
}

// ---------------- host launcher --------------------------------------------
static void* symp(const void* sym) {
    void* p = nullptr;
    cudaGetSymbolAddress(&p, sym);
    return p;
}

extern "C" void kernel_launch(void* const* d_in, const int* in_sizes, int n_in,
                              void* d_out, int out_size)
{
    (void)in_sizes; (void)n_in; (void)out_size;
    const float* midq  = (const float*)d_in[0];
    const float* midk  = (const float*)d_in[1];
    const int*   lq    = (const int*)d_in[2];
    const int*   lk    = (const int*)d_in[3];
    const float* W1    = (const float*)d_in[4];
    const float* b1    = (const float*)d_in[5];
    const float* gamma = (const float*)d_in[6];
    const float* beta  = (const float*)d_in[7];
    const float* W2    = (const float*)d_in[8];
    const float* b2    = (const float*)d_in[9];
    const float* Wlin  = (const float*)d_in[10];
    const float* blin  = (const float*)d_in[11];
    const float* negq  = (const float*)d_in[12];
    const float* posq  = (const float*)d_in[13];
    const int*   nptr  = (const int*)d_in[14];
    const int*   pptr  = (const int*)d_in[15];
    float* out = (float*)d_out;

    float*  Hq     = (float*)symp(g_Hq);
    float*  Hk     = (float*)symp(g_Hk);
    __half* midqH  = (__half*)symp(g_midqH);
    __half* midkH  = (__half*)symp(g_midkH);
    __half* HqH    = (__half*)symp(g_HqH);
    __half* HkH    = (__half*)symp(g_HkH);
    __half* W1T    = (__half*)symp(g_W1T);
    __half* WlinT  = (__half*)symp(g_WlinT);
    __half* W2T    = (__half*)symp(g_W2T);
    __half* negT   = (__half*)symp(g_negT);
    float*  scq = (float*)symp(g_scq); float* shq = (float*)symp(g_shq);
    float*  sck = (float*)symp(g_sck); float* shk = (float*)symp(g_shk);
    __half* fqH = (__half*)symp(g_featqH);
    __half* fkH = (__half*)symp(g_featkH);
    float*  fpart = (float*)symp(g_fpart);

    cudaFuncSetAttribute(hgemm_k<0>, cudaFuncAttributeMaxDynamicSharedMemorySize, SMEM_BYTES);
    cudaFuncSetAttribute(hgemm_k<2>, cudaFuncAttributeMaxDynamicSharedMemorySize, SMEM_BYTES);
    cudaFuncSetAttribute(hgemm_k<3>, cudaFuncAttributeMaxDynamicSharedMemorySize, SMEM_BYTES);
    cudaFuncSetAttribute(hgemm_k<4>, cudaFuncAttributeMaxDynamicSharedMemorySize, SMEM_BYTES);

    // static fork stream + events (created once, outside graph capture;
    // non-blocking stream so the legacy default stream doesn't implicitly sync)
    static cudaStream_t s2 = nullptr;
    static cudaEvent_t evFork = nullptr, evJoin = nullptr;
    if (!s2) {
        cudaStreamCreateWithFlags(&s2, cudaStreamNonBlocking);
        cudaEventCreateWithFlags(&evFork, cudaEventDisableTiming);
        cudaEventCreateWithFlags(&evJoin, cudaEventDisableTiming);
    }

    // ---- default stream: prep shared by both branches ----
    cvt_half_k<<<dim3(Bsz * DF / 8 / 256, 1, 2), 256>>>(
        midq, midk, midqH, midkH, Bsz * DF / 8);
    transpose_half_k<<<dim3(CC / 32, DF / 32), dim3(32, 8)>>>(Wlin, WlinT, DF, CC);

    // ---- fork: s2 runs queue memcpys + the independent Wlin logits GEMM ----
    cudaEventRecord(evFork, 0);
    cudaStreamWaitEvent(s2, evFork, 0);
    cudaMemcpyAsync(out + OFF_NQ2, negq, sizeof(float) * (size_t)DIM * NC,
                    cudaMemcpyDeviceToDevice, s2);
    cudaMemcpyAsync(out + OFF_PQ2, posq, sizeof(float) * (size_t)DIM * PC,
                    cudaMemcpyDeviceToDevice, s2);
    hgemm_k<0><<<dim3(CC / 128, Bsz / 128, 2), 256, SMEM_BYTES, s2>>>(
        midqH, midkH, WlinT, blin, out + OFF_LQ, out + OFF_LK,
        DF, CC, nullptr, nullptr, nullptr);
    cudaEventRecord(evJoin, s2);

    // ---- default stream: the dependency chain ----
    transpose_half_k<<<dim3(DF / 32, DF / 32), dim3(32, 8)>>>(W1, W1T, DF, DF);
    transpose_half_k<<<dim3(DIM / 32, DF / 32), dim3(32, 8)>>>(W2, W2T, DF, DIM);
    transpose_half_k<<<dim3(NC / 32, DIM / 32), dim3(32, 8)>>>(negq, negT, DIM, NC);

    // H = mid @ W1 + b1
    hgemm_k<0><<<dim3(DF / 128, Bsz / 128, 2), 256, SMEM_BYTES>>>(
        midqH, midkH, W1T, b1, Hq, Hk, DF, DF, nullptr, nullptr, nullptr);

    // BN stats + apply(relu) -> half
    bn_stats_k<<<dim3(DF / 32, 1, 2), dim3(32, 32)>>>(
        Hq, Hk, gamma, beta, scq, shq, sck, shk);
    bnrelu_half_k<<<dim3(Bsz * DF / 8 / 256, 1, 2), 256>>>(Hq, Hk, HqH, HkH);

    // feat partials = relu(BN(H)) @ W2 (split-K 16, q/k via z)
    hgemm_k<2><<<dim3(1, Bsz / 128, 2 * SPLITK), 256, SMEM_BYTES>>>(
        HqH, HkH, W2T, nullptr, fpart, nullptr, DF, DIM,
        nullptr, nullptr, nullptr);

    // reduce + bias + l2norm (fp32 + half feats)
    reduce_l2_k<<<dim3(Bsz, 2), DIM>>>(b2);

    // sim_batch = feat_q @ feat_k^T (+ labels fused)
    hgemm_k<3><<<dim3(Bsz / 128, Bsz / 128, 1), 256, SMEM_BYTES>>>(
        fqH, nullptr, fkH, nullptr, out + OFF_SIM, nullptr, DIM, SIMW,
        lq, lk, out + OFF_LAB);

    // pos_list (+ ones)
    pos_k<<<Bsz, 256>>>(lq, posq, out);

    // neg gathered (+ zeros into labels)
    hgemm_k<4><<<dim3(NC / 128, Bsz / 128, 1), 256, SMEM_BYTES>>>(
        fqH, nullptr, negT, nullptr, out + OFF_SIM + Bsz + PP, nullptr,
        DIM, SIMW, lq, nullptr, out + OFF_LAB + Bsz + PP);

    // queue update machinery (queue_update depends on s2's memcpys: join first)
    rank_k<<<32, dim3(32, 32)>>>(lk);
    ptr_k<<<CC / 8, 256>>>(lk, nptr, pptr, out);
    cudaStreamWaitEvent(0, evJoin, 0);
    queue_update_k<<<Bsz, DIM>>>(lk, nptr, pptr, out);
}

// round 15
// speedup vs baseline: 1.2130x; 1.0970x over previous
#include <cuda_runtime.h>
#include <cuda_fp16.h>
#include <cstddef>
#include <cstdint>

#define Bsz   1024
#define DF    2048
#define DIM   128
#define CC    8192
#define PP    8
#define NNq   4
#define NC    (NNq * CC)            // 32768
#define PC    (PP * CC)             // 65536
#define SIMW  (Bsz + PP + NNq * (CC - 1))  // 33796
#define SPLITK 16

static constexpr size_t OFF_SIM  = 0;
static constexpr size_t OFF_LAB  = (size_t)Bsz * SIMW;
static constexpr size_t OFF_LQ   = OFF_LAB + (size_t)Bsz * SIMW;
static constexpr size_t OFF_LK   = OFF_LQ + (size_t)Bsz * CC;
static constexpr size_t OFF_NQ2  = OFF_LK + (size_t)Bsz * CC;
static constexpr size_t OFF_PQ2  = OFF_NQ2 + (size_t)DIM * NC;
static constexpr size_t OFF_NPTR = OFF_PQ2 + (size_t)DIM * PC;
static constexpr size_t OFF_PPTR = OFF_NPTR + CC;

// ---------------- device scratch (16B-aligned for cp.async) ---------------
__device__ __align__(16) float  g_Hq[(size_t)Bsz * DF];
__device__ __align__(16) float  g_Hk[(size_t)Bsz * DF];
__device__ __align__(16) __half g_midqH[(size_t)Bsz * DF];
__device__ __align__(16) __half g_midkH[(size_t)Bsz * DF];
__device__ __align__(16) __half g_HqH[(size_t)Bsz * DF];     // relu(BN(H)) half
__device__ __align__(16) __half g_HkH[(size_t)Bsz * DF];
__device__ __align__(16) __half g_W1T[(size_t)DF * DF];      // [N][K] half
__device__ __align__(16) __half g_WlinT[(size_t)CC * DF];
__device__ __align__(16) __half g_W2T[(size_t)DIM * DF];
__device__ __align__(16) __half g_negT[(size_t)NC * DIM];
__device__ float g_scq[DF], g_shq[DF], g_sck[DF], g_shk[DF];
__device__ float g_featq[(size_t)Bsz * DIM];
__device__ float g_featk[(size_t)Bsz * DIM];
__device__ __align__(16) __half g_featqH[(size_t)Bsz * DIM];
__device__ __align__(16) __half g_featkH[(size_t)Bsz * DIM];
__device__ float g_fpart[(size_t)2 * SPLITK * Bsz * DIM];
__device__ int   g_rank[Bsz];
__device__ int   g_cntb[Bsz];

// ---------------- helpers -------------------------------------------------
__device__ __forceinline__ void mma_f16(float c[4], const unsigned a[4],
                                        const unsigned b[2]) {
    asm volatile(
        "mma.sync.aligned.m16n8k16.row.col.f32.f16.f16.f32 "
        "{%0,%1,%2,%3}, {%4,%5,%6,%7}, {%8,%9}, {%0,%1,%2,%3};"
        : "+f"(c[0]), "+f"(c[1]), "+f"(c[2]), "+f"(c[3])
        : "r"(a[0]), "r"(a[1]), "r"(a[2]), "r"(a[3]), "r"(b[0]), "r"(b[1]));
}

__device__ __forceinline__ void ldsm_x4(unsigned r[4], uint32_t addr) {
    asm volatile("ldmatrix.sync.aligned.m8n8.x4.shared.b16 {%0,%1,%2,%3}, [%4];"
                 : "=r"(r[0]), "=r"(r[1]), "=r"(r[2]), "=r"(r[3]) : "r"(addr));
}
// B stored [N][K]: mma b-frag wants stored(n=l>>2, k=2(l&3)+{0,1}) — the
// NON-trans ldmatrix mapping.
__device__ __forceinline__ void ldsm_x2(unsigned r[2], uint32_t addr) {
    asm volatile("ldmatrix.sync.aligned.m8n8.x2.shared.b16 {%0,%1}, [%2];"
                 : "=r"(r[0]), "=r"(r[1]) : "r"(addr));
}

__device__ __forceinline__ void cpa16(uint32_t saddr, const void* g) {
    asm volatile("cp.async.cg.shared.global [%0], [%1], 16;\n"
                 :: "r"(saddr), "l"(g));
}
#define CP_COMMIT() asm volatile("cp.async.commit_group;\n" ::: "memory")
#define CP_WAIT1()  asm volatile("cp.async.wait_group 1;\n" ::: "memory")

// ---------------- FP16 tensor-core GEMM, 3-stage cp.async -----------------
// 128x128 tile, BK=32 (halfs), 256 threads (8 warps, warp tile 64x32).
// A [M][K] half, Bt [N][K] half (K-major; shared staging path).
// Smem rows of 40 halfs (80B pitch): ldmatrix row banks 20r mod 32 —
// conflict-free; rows 16B-aligned. 3 stages, one barrier per iteration.
// Labels plane is pre-zeroed by memset: MODE 3 writes ONLY the ones (rare);
// MODE 4 writes no labels at all.
// MODE 0: C = A@B + bias; z selects (A0,C0)/(A1,C1)
// MODE 2: split-K partial: z = qk*SPLITK + sk; C = C0 + z*Bsz*DIM
// MODE 3: plain; writes 1.0f into Lab where lkk[n]==lqq[m]
// MODE 4: neg scatter skipping lqq[m]'s NNq cols
#define BK    32
#define HSTR  40
#define TILEH (128 * HSTR)        // 5120 halfs per tile
#define STAGEH (2 * TILEH)        // 10240 halfs per stage (A + B)
#define SMEM_BYTES (3 * STAGEH * 2)   // 61440
template <int MODE>
__global__ __launch_bounds__(256, 2) void hgemm_k(
    const __half* __restrict__ A0, const __half* __restrict__ A1,
    const __half* __restrict__ Bt, const float* __restrict__ bias,
    float* __restrict__ C0, float* __restrict__ C1,
    int K, int ldc,
    const int* __restrict__ lqq, const int* __restrict__ lkk,
    float* __restrict__ Lab)
{
    extern __shared__ __align__(16) __half smem[];

    const int tid   = threadIdx.x;
    const int mBase = blockIdx.y * 128;
    const int nBase = blockIdx.x * 128;
    const int lane  = tid & 31;
    const int warp  = tid >> 5;
    const int g     = lane >> 2;
    const int tig   = lane & 3;
    const int wm    = (warp & 1) * 64;
    const int wn    = (warp >> 1) * 32;

    int kBeg = 0, kEnd = K;
    const __half* A;
    float* Cc;
    if (MODE == 2) {
        int qk  = blockIdx.z >> 4;
        int skc = blockIdx.z & 15;
        kBeg = skc * (K / SPLITK);
        kEnd = kBeg + K / SPLITK;
        A  = qk ? A1 : A0;
        Cc = C0 + (size_t)blockIdx.z * ((size_t)Bsz * DIM);
    } else {
        A  = blockIdx.z ? A1 : A0;
        Cc = blockIdx.z ? C1 : C0;
    }

    uint32_t sbase = (uint32_t)__cvta_generic_to_shared(smem);

    // ldmatrix per-lane address components
    const int a_row = wm + (lane & 7) + ((lane >> 3) & 1) * 8;  // + mt*16
    const int a_kof = (lane >> 4) << 3;                         // 0 or 8
    const int b_row = wn + (lane & 7);                          // + nt*8
    const int b_kof = ((lane >> 3) & 1) << 3;                   // 0 or 8

    // staging: each row = 32 halfs = 4 x 16B chunks; 2 threads/row, 2 each
    const int sr = tid >> 1;
    const int cb = (tid & 1) * 2;
    auto load_tiles = [&](int s, int kpos) {
        const __half* srcA = A  + (size_t)(mBase + sr) * K + kpos;
        const __half* srcB = Bt + (size_t)(nBase + sr) * K + kpos;
        uint32_t rowA = sbase + (uint32_t)((s * STAGEH + sr * HSTR) * 2);
        uint32_t rowB = rowA + (uint32_t)(TILEH * 2);
        #pragma unroll
        for (int i = 0; i < 2; i++) {
            int c = cb + i;
            cpa16(rowA + (uint32_t)(c * 16), srcA + c * 8);
            cpa16(rowB + (uint32_t)(c * 16), srcB + c * 8);
        }
    };

    float acc[4][4][4] = {};

    const int nIter = (kEnd - kBeg) / BK;
    load_tiles(0, kBeg);
    CP_COMMIT();
    if (nIter > 1) load_tiles(1, kBeg + BK);
    CP_COMMIT();

    for (int it = 0; it < nIter; ++it) {
        CP_WAIT1();            // stage it retired (tail groups are empty)
        __syncthreads();       // publish stage it; retire reads of (it+2)%3
        if (it + 2 < nIter) load_tiles((it + 2) % 3, kBeg + (it + 2) * BK);
        CP_COMMIT();

        const uint32_t aS = sbase + (uint32_t)((it % 3) * STAGEH * 2);
        const uint32_t bS = aS + (uint32_t)(TILEH * 2);
        #pragma unroll
        for (int kk = 0; kk < BK; kk += 16) {
            unsigned af[4][4], bf[4][2];
            #pragma unroll
            for (int mt = 0; mt < 4; mt++)
                ldsm_x4(af[mt],
                        aS + (uint32_t)(((a_row + mt * 16) * HSTR + kk + a_kof) * 2));
            #pragma unroll
            for (int nt = 0; nt < 4; nt++)
                ldsm_x2(bf[nt],
                        bS + (uint32_t)(((b_row + nt * 8) * HSTR + kk + b_kof) * 2));
            #pragma unroll
            for (int mt = 0; mt < 4; mt++)
                #pragma unroll
                for (int nt = 0; nt < 4; nt++)
                    mma_f16(acc[mt][nt], af[mt], bf[nt]);
        }
    }
    __syncthreads();

    // ---- epilogue ----
    #pragma unroll
    for (int mt = 0; mt < 4; mt++) {
        int r0 = mBase + wm + mt * 16 + g;
        int r1 = r0 + 8;
        int la0 = 0, la1 = 0, lb0 = 0, lb1 = 0;
        if (MODE == 4) { la0 = lqq[r0] * NNq; la1 = lqq[r1] * NNq; }
        if (MODE == 3) { lb0 = lqq[r0]; lb1 = lqq[r1]; }
        #pragma unroll
        for (int nt = 0; nt < 4; nt++) {
            int c = nBase + wn + nt * 8 + 2 * tig;
            const float* a4 = acc[mt][nt];
            if (MODE == 4) {
                int n0 = c, n1 = c + 1;
                if (n0 < la0)             Cc[(size_t)r0 * ldc + n0]       = a4[0];
                else if (n0 >= la0 + NNq) Cc[(size_t)r0 * ldc + n0 - NNq] = a4[0];
                if (n1 < la0)             Cc[(size_t)r0 * ldc + n1]       = a4[1];
                else if (n1 >= la0 + NNq) Cc[(size_t)r0 * ldc + n1 - NNq] = a4[1];
                if (n0 < la1)             Cc[(size_t)r1 * ldc + n0]       = a4[2];
                else if (n0 >= la1 + NNq) Cc[(size_t)r1 * ldc + n0 - NNq] = a4[2];
                if (n1 < la1)             Cc[(size_t)r1 * ldc + n1]       = a4[3];
                else if (n1 >= la1 + NNq) Cc[(size_t)r1 * ldc + n1 - NNq] = a4[3];
            } else {
                float bx = 0.f, by = 0.f;
                if (MODE == 0) { bx = bias[c]; by = bias[c + 1]; }
                float2 v0 = { a4[0] + bx, a4[1] + by };
                float2 v1 = { a4[2] + bx, a4[3] + by };
                *(float2*)(Cc + (size_t)r0 * ldc + c) = v0;
                *(float2*)(Cc + (size_t)r1 * ldc + c) = v1;
                if (MODE == 3) {
                    // labels plane pre-zeroed: store only the rare ones
                    int k0c = lkk[c], k1c = lkk[c + 1];
                    if (k0c == lb0) Lab[(size_t)r0 * ldc + c]     = 1.f;
                    if (k1c == lb0) Lab[(size_t)r0 * ldc + c + 1] = 1.f;
                    if (k0c == lb1) Lab[(size_t)r1 * ldc + c]     = 1.f;
                    if (k1c == lb1) Lab[(size_t)r1 * ldc + c + 1] = 1.f;
                }
            }
        }
    }
}

// ---------------- prep: fp32 -> fp16 (8 / thread; q/k via z) ---------------
__global__ void cvt_half_k(const float* __restrict__ in0, const float* __restrict__ in1,
                           __half* __restrict__ o0, __half* __restrict__ o1, int n8)
{
    const float* in = blockIdx.z ? in1 : in0;
    __half* o = blockIdx.z ? o1 : o0;
    int i = blockIdx.x * blockDim.x + threadIdx.x;
    if (i >= n8) return;
    float4 a = ((const float4*)in)[i * 2];
    float4 b = ((const float4*)in)[i * 2 + 1];
    __half h[8];
    h[0] = __float2half_rn(a.x); h[1] = __float2half_rn(a.y);
    h[2] = __float2half_rn(a.z); h[3] = __float2half_rn(a.w);
    h[4] = __float2half_rn(b.x); h[5] = __float2half_rn(b.y);
    h[6] = __float2half_rn(b.z); h[7] = __float2half_rn(b.w);
    ((uint4*)o)[i] = *(const uint4*)h;
}

// ---------------- prep: transpose fp32 [R][C] -> half [C][R] ---------------
__global__ void transpose_half_k(const float* __restrict__ in, __half* __restrict__ out,
                                 int R, int C)
{
    __shared__ float t[32][33];
    int cx = blockIdx.x * 32 + threadIdx.x;
    int ry = blockIdx.y * 32 + threadIdx.y;
    #pragma unroll
    for (int j = 0; j < 32; j += 8)
        t[threadIdx.y + j][threadIdx.x] = in[(size_t)(ry + j) * C + cx];
    __syncthreads();
    int cx2 = blockIdx.y * 32 + threadIdx.x;
    int ry2 = blockIdx.x * 32 + threadIdx.y;
    #pragma unroll
    for (int j = 0; j < 32; j += 8)
        out[(size_t)(ry2 + j) * R + cx2] = __float2half_rn(t[threadIdx.x][threadIdx.y + j]);
}

// ---------------- BN stats -------------------------------------------------
__global__ void bn_stats_k(const float* __restrict__ Hq, const float* __restrict__ Hk,
                           const float* __restrict__ gamma, const float* __restrict__ beta,
                           float* __restrict__ scq, float* __restrict__ shq,
                           float* __restrict__ sck, float* __restrict__ shk)
{
    const float* H = blockIdx.z ? Hk : Hq;
    float* scale = blockIdx.z ? sck : scq;
    float* shift = blockIdx.z ? shk : shq;
    int f = blockIdx.x * 32 + threadIdx.x;
    float s = 0.f, ss = 0.f;
    for (int r = threadIdx.y; r < Bsz; r += 32) {
        float v = H[(size_t)r * DF + f];
        s += v; ss += v * v;
    }
    __shared__ float sh_s[32][33], sh_ss[32][33];
    sh_s[threadIdx.y][threadIdx.x]  = s;
    sh_ss[threadIdx.y][threadIdx.x] = ss;
    __syncthreads();
    if (threadIdx.y == 0) {
        #pragma unroll
        for (int y = 1; y < 32; y++) {
            s += sh_s[y][threadIdx.x]; ss += sh_ss[y][threadIdx.x];
        }
        float mu  = s * (1.f / Bsz);
        float var = ss * (1.f / Bsz) - mu * mu;
        float rst = rsqrtf(var + 1e-5f);
        float scv = rst * gamma[f];
        scale[f] = scv;
        shift[f] = beta[f] - mu * scv;
    }
}

// ---------------- BN apply + relu -> half ----------------------------------
__global__ void bnrelu_half_k(const float* __restrict__ Hq, const float* __restrict__ Hk,
                              __half* __restrict__ Rq, __half* __restrict__ Rk)
{
    const float* H = blockIdx.z ? Hk : Hq;
    __half* R = blockIdx.z ? Rk : Rq;
    const float* sc = blockIdx.z ? g_sck : g_scq;
    const float* sh = blockIdx.z ? g_shk : g_shq;
    int i = blockIdx.x * blockDim.x + threadIdx.x;   // 8-float group
    int f = (i * 8) & (DF - 1);
    float4 a = ((const float4*)H)[i * 2];
    float4 b = ((const float4*)H)[i * 2 + 1];
    float4 sa = *(const float4*)(sc + f);
    float4 sb = *(const float4*)(sc + f + 4);
    float4 ha = *(const float4*)(sh + f);
    float4 hb = *(const float4*)(sh + f + 4);
    __half h[8];
    h[0] = __float2half_rn(fmaxf(fmaf(a.x, sa.x, ha.x), 0.f));
    h[1] = __float2half_rn(fmaxf(fmaf(a.y, sa.y, ha.y), 0.f));
    h[2] = __float2half_rn(fmaxf(fmaf(a.z, sa.z, ha.z), 0.f));
    h[3] = __float2half_rn(fmaxf(fmaf(a.w, sa.w, ha.w), 0.f));
    h[4] = __float2half_rn(fmaxf(fmaf(b.x, sb.x, hb.x), 0.f));
    h[5] = __float2half_rn(fmaxf(fmaf(b.y, sb.y, hb.y), 0.f));
    h[6] = __float2half_rn(fmaxf(fmaf(b.z, sb.z, hb.z), 0.f));
    h[7] = __float2half_rn(fmaxf(fmaf(b.w, sb.w, hb.w), 0.f));
    ((uint4*)R)[i] = *(const uint4*)h;
}

// ---------------- split-K reduce + bias + l2norm ---------------------------
__global__ void reduce_l2_k(const float* __restrict__ b2)
{
    int qk = blockIdx.y, b = blockIdx.x, d = threadIdx.x;  // d: 0..127
    const float* part = g_fpart + (size_t)qk * SPLITK * Bsz * DIM;
    float v = b2[d];
    #pragma unroll
    for (int s = 0; s < SPLITK; s++)
        v += part[(size_t)s * Bsz * DIM + (size_t)b * DIM + d];
    float ss = v * v;
    #pragma unroll
    for (int o = 16; o; o >>= 1) ss += __shfl_xor_sync(0xffffffffu, ss, o);
    __shared__ float ws[4];
    if ((d & 31) == 0) ws[d >> 5] = ss;
    __syncthreads();
    ss = ws[0] + ws[1] + ws[2] + ws[3];
    float inv = 1.f / fmaxf(sqrtf(ss), 1e-12f);
    float vn = v * inv;
    if (qk) {
        g_featk[(size_t)b * DIM + d] = vn;
        g_featkH[(size_t)b * DIM + d] = __float2half_rn(vn);
    } else {
        g_featq[(size_t)b * DIM + d] = vn;
        g_featqH[(size_t)b * DIM + d] = __float2half_rn(vn);
    }
}

// ---------------- pos_list (+ ones into labels) ----------------------------
__global__ void pos_k(const int* __restrict__ lq, const float* __restrict__ posq,
                      float* __restrict__ out)
{
    int b = blockIdx.x, tid = threadIdx.x;
    __shared__ float fr[DIM];
    if (tid < DIM) fr[tid] = g_featq[(size_t)b * DIM + tid];
    __syncthreads();
    int w = tid >> 5, lane = tid & 31;
    int col = lq[b] * PP + w;
    float s = 0.f;
    for (int d = lane; d < DIM; d += 32)
        s += fr[d] * posq[(size_t)d * PC + col];
    #pragma unroll
    for (int o = 16; o; o >>= 1) s += __shfl_down_sync(0xffffffffu, s, o);
    if (lane == 0) {
        out[OFF_SIM + (size_t)b * SIMW + Bsz + w] = s;
        out[OFF_LAB + (size_t)b * SIMW + Bsz + w] = 1.f;
    }
}

// ---------------- occurrence rank + count (warp-per-row) -------------------
__global__ void rank_k(const int* __restrict__ lk)
{
    __shared__ int sl[Bsz];
    int t = threadIdx.y * 32 + threadIdx.x;
    for (int i = t; i < Bsz; i += 1024) sl[i] = lk[i];
    __syncthreads();
    int b = blockIdx.x * 32 + threadIdx.y;
    int lab = sl[b];
    int r = 0, c = 0;
    for (int j = threadIdx.x; j < Bsz; j += 32) {
        int e = (sl[j] == lab);
        c += e;
        r += e & (j < b);
    }
    #pragma unroll
    for (int o = 16; o; o >>= 1) {
        c += __shfl_down_sync(0xffffffffu, c, o);
        r += __shfl_down_sync(0xffffffffu, r, o);
    }
    if (threadIdx.x == 0) { g_rank[b] = r; g_cntb[b] = c; }
}

// ---------------- ptr outputs (warp-per-class) -----------------------------
__global__ void ptr_k(const int* __restrict__ lk, const int* __restrict__ nptr,
                      const int* __restrict__ pptr, float* __restrict__ out)
{
    __shared__ int sl[Bsz];
    for (int i = threadIdx.x; i < Bsz; i += 256) sl[i] = lk[i];
    __syncthreads();
    int w = threadIdx.x >> 5, lane = threadIdx.x & 31;
    int c = blockIdx.x * 8 + w;
    int cnt = 0;
    for (int j = lane; j < Bsz; j += 32) cnt += (sl[j] == c);
    #pragma unroll
    for (int o = 16; o; o >>= 1) cnt += __shfl_down_sync(0xffffffffu, cnt, o);
    if (lane == 0) {
        out[OFF_NPTR + c] = (float)((nptr[c] + cnt) % NNq);
        out[OFF_PPTR + c] = (float)((pptr[c] + cnt) % PP);
    }
}

// ---------------- queue overwrite ------------------------------------------
__global__ void queue_update_k(const int* __restrict__ lk, const int* __restrict__ nptr,
                               const int* __restrict__ pptr, float* __restrict__ out)
{
    int b = blockIdx.x;
    int d = threadIdx.x;   // 128
    int lab = lk[b];
    int r = g_rank[b];
    int c = g_cntb[b];
    float v = g_featk[(size_t)b * DIM + d];
    if (r >= c - NNq) {
        int slot = (nptr[lab] + r) % NNq;
        out[OFF_NQ2 + (size_t)d * NC + lab * NNq + slot] = v;
    }
    if (r >= c - PP) {
        int slot = (pptr[lab] + r) % PP;
        out[OFF_PQ2 + (size_t)d * PC + lab * PP + slot] = v;
    }
}

// ---------------- host launcher --------------------------------------------
static void* symp(const void* sym) {
    void* p = nullptr;
    cudaGetSymbolAddress(&p, sym);
    return p;
}

extern "C" void kernel_launch(void* const* d_in, const int* in_sizes, int n_in,
                              void* d_out, int out_size)
{
    (void)in_sizes; (void)n_in; (void)out_size;
    const float* midq  = (const float*)d_in[0];
    const float* midk  = (const float*)d_in[1];
    const int*   lq    = (const int*)d_in[2];
    const int*   lk    = (const int*)d_in[3];
    const float* W1    = (const float*)d_in[4];
    const float* b1    = (const float*)d_in[5];
    const float* gamma = (const float*)d_in[6];
    const float* beta  = (const float*)d_in[7];
    const float* W2    = (const float*)d_in[8];
    const float* b2    = (const float*)d_in[9];
    const float* Wlin  = (const float*)d_in[10];
    const float* blin  = (const float*)d_in[11];
    const float* negq  = (const float*)d_in[12];
    const float* posq  = (const float*)d_in[13];
    const int*   nptr  = (const int*)d_in[14];
    const int*   pptr  = (const int*)d_in[15];
    float* out = (float*)d_out;

    float*  Hq     = (float*)symp(g_Hq);
    float*  Hk     = (float*)symp(g_Hk);
    __half* midqH  = (__half*)symp(g_midqH);
    __half* midkH  = (__half*)symp(g_midkH);
    __half* HqH    = (__half*)symp(g_HqH);
    __half* HkH    = (__half*)symp(g_HkH);
    __half* W1T    = (__half*)symp(g_W1T);
    __half* WlinT  = (__half*)symp(g_WlinT);
    __half* W2T    = (__half*)symp(g_W2T);
    __half* negT   = (__half*)symp(g_negT);
    float*  scq = (float*)symp(g_scq); float* shq = (float*)symp(g_shq);
    float*  sck = (float*)symp(g_sck); float* shk = (float*)symp(g_shk);
    __half* fqH = (__half*)symp(g_featqH);
    __half* fkH = (__half*)symp(g_featkH);
    float*  fpart = (float*)symp(g_fpart);

    cudaFuncSetAttribute(hgemm_k<0>, cudaFuncAttributeMaxDynamicSharedMemorySize, SMEM_BYTES);
    cudaFuncSetAttribute(hgemm_k<2>, cudaFuncAttributeMaxDynamicSharedMemorySize, SMEM_BYTES);
    cudaFuncSetAttribute(hgemm_k<3>, cudaFuncAttributeMaxDynamicSharedMemorySize, SMEM_BYTES);
    cudaFuncSetAttribute(hgemm_k<4>, cudaFuncAttributeMaxDynamicSharedMemorySize, SMEM_BYTES);

    // static fork stream + events (created once, outside graph capture)
    static cudaStream_t s2 = nullptr;
    static cudaEvent_t evFork = nullptr, evJoin = nullptr, evLab = nullptr;
    if (!s2) {
        cudaStreamCreateWithFlags(&s2, cudaStreamNonBlocking);
        cudaEventCreateWithFlags(&evFork, cudaEventDisableTiming);
        cudaEventCreateWithFlags(&evJoin, cudaEventDisableTiming);
        cudaEventCreateWithFlags(&evLab, cudaEventDisableTiming);
    }

    // ---- default stream: prep shared by both branches ----
    cvt_half_k<<<dim3(Bsz * DF / 8 / 256, 1, 2), 256>>>(
        midq, midk, midqH, midkH, Bsz * DF / 8);
    transpose_half_k<<<dim3(CC / 32, DF / 32), dim3(32, 8)>>>(Wlin, WlinT, DF, CC);

    // ---- fork: s2 zeroes labels, copies queues, runs the Wlin GEMM ----
    cudaEventRecord(evFork, 0);
    cudaStreamWaitEvent(s2, evFork, 0);
    cudaMemsetAsync(out + OFF_LAB, 0, sizeof(float) * (size_t)Bsz * SIMW, s2);
    cudaEventRecord(evLab, s2);
    cudaMemcpyAsync(out + OFF_NQ2, negq, sizeof(float) * (size_t)DIM * NC,
                    cudaMemcpyDeviceToDevice, s2);
    cudaMemcpyAsync(out + OFF_PQ2, posq, sizeof(float) * (size_t)DIM * PC,
                    cudaMemcpyDeviceToDevice, s2);
    hgemm_k<0><<<dim3(CC / 128, Bsz / 128, 2), 256, SMEM_BYTES, s2>>>(
        midqH, midkH, WlinT, blin, out + OFF_LQ, out + OFF_LK,
        DF, CC, nullptr, nullptr, nullptr);
    cudaEventRecord(evJoin, s2);

    // ---- default stream: the dependency chain ----
    transpose_half_k<<<dim3(DF / 32, DF / 32), dim3(32, 8)>>>(W1, W1T, DF, DF);
    transpose_half_k<<<dim3(DIM / 32, DF / 32), dim3(32, 8)>>>(W2, W2T, DF, DIM);
    transpose_half_k<<<dim3(NC / 32, DIM / 32), dim3(32, 8)>>>(negq, negT, DIM, NC);

    // H = mid @ W1 + b1
    hgemm_k<0><<<dim3(DF / 128, Bsz / 128, 2), 256, SMEM_BYTES>>>(
        midqH, midkH, W1T, b1, Hq, Hk, DF, DF, nullptr, nullptr, nullptr);

    // BN stats + apply(relu) -> half
    bn_stats_k<<<dim3(DF / 32, 1, 2), dim3(32, 32)>>>(
        Hq, Hk, gamma, beta, scq, shq, sck, shk);
    bnrelu_half_k<<<dim3(Bsz * DF / 8 / 256, 1, 2), 256>>>(Hq, Hk, HqH, HkH);

    // feat partials = relu(BN(H)) @ W2 (split-K 16, q/k via z)
    hgemm_k<2><<<dim3(1, Bsz / 128, 2 * SPLITK), 256, SMEM_BYTES>>>(
        HqH, HkH, W2T, nullptr, fpart, nullptr, DF, DIM,
        nullptr, nullptr, nullptr);

    // reduce + bias + l2norm (fp32 + half feats)
    reduce_l2_k<<<dim3(Bsz, 2), DIM>>>(b2);

    // labels plane must be zeroed before the sparse ones are written
    cudaStreamWaitEvent(0, evLab, 0);

    // sim_batch = feat_q @ feat_k^T (+ sparse label ones)
    hgemm_k<3><<<dim3(Bsz / 128, Bsz / 128, 1), 256, SMEM_BYTES>>>(
        fqH, nullptr, fkH, nullptr, out + OFF_SIM, nullptr, DIM, SIMW,
        lq, lk, out + OFF_LAB);

    // pos_list (+ ones)
    pos_k<<<Bsz, 256>>>(lq, posq, out);

    // neg gathered (labels already zero — no label writes)
    hgemm_k<4><<<dim3(NC / 128, Bsz / 128, 1), 256, SMEM_BYTES>>>(
        fqH, nullptr, negT, nullptr, out + OFF_SIM + Bsz + PP, nullptr,
        DIM, SIMW, lq, nullptr, nullptr);

    // queue update machinery (queue_update depends on s2's memcpys: join first)
    rank_k<<<32, dim3(32, 32)>>>(lk);
    ptr_k<<<CC / 8, 256>>>(lk, nptr, pptr, out);
    cudaStreamWaitEvent(0, evJoin, 0);
    queue_update_k<<<Bsz, DIM>>>(lk, nptr, pptr, out);
}

// round 16
// speedup vs baseline: 1.2304x; 1.0144x over previous
#include <cuda_runtime.h>
#include <cuda_fp16.h>
#include <cstddef>
#include <cstdint>

#define Bsz   1024
#define DF    2048
#define DIM   128
#define CC    8192
#define PP    8
#define NNq   4
#define NC    (NNq * CC)            // 32768
#define PC    (PP * CC)             // 65536
#define SIMW  (Bsz + PP + NNq * (CC - 1))  // 33796
#define SPLITK 16

static constexpr size_t OFF_SIM  = 0;
static constexpr size_t OFF_LAB  = (size_t)Bsz * SIMW;
static constexpr size_t OFF_LQ   = OFF_LAB + (size_t)Bsz * SIMW;
static constexpr size_t OFF_LK   = OFF_LQ + (size_t)Bsz * CC;
static constexpr size_t OFF_NQ2  = OFF_LK + (size_t)Bsz * CC;
static constexpr size_t OFF_PQ2  = OFF_NQ2 + (size_t)DIM * NC;
static constexpr size_t OFF_NPTR = OFF_PQ2 + (size_t)DIM * PC;
static constexpr size_t OFF_PPTR = OFF_NPTR + CC;

// ---------------- device scratch (16B-aligned for cp.async) ---------------
__device__ __align__(16) float  g_Hq[(size_t)Bsz * DF];
__device__ __align__(16) float  g_Hk[(size_t)Bsz * DF];
__device__ __align__(16) __half g_midqH[(size_t)Bsz * DF];
__device__ __align__(16) __half g_midkH[(size_t)Bsz * DF];
__device__ __align__(16) __half g_HqH[(size_t)Bsz * DF];     // relu(BN(H)) half
__device__ __align__(16) __half g_HkH[(size_t)Bsz * DF];
__device__ __align__(16) __half g_W1T[(size_t)DF * DF];      // [N][K] half
__device__ __align__(16) __half g_WlinT[(size_t)CC * DF];
__device__ __align__(16) __half g_W2T[(size_t)DIM * DF];
__device__ __align__(16) __half g_negT[(size_t)NC * DIM];
__device__ float g_scq[DF], g_shq[DF], g_sck[DF], g_shk[DF];
__device__ float g_featq[(size_t)Bsz * DIM];
__device__ float g_featk[(size_t)Bsz * DIM];
__device__ __align__(16) __half g_featqH[(size_t)Bsz * DIM];
__device__ __align__(16) __half g_featkH[(size_t)Bsz * DIM];
__device__ float g_fpart[(size_t)2 * SPLITK * Bsz * DIM];
__device__ int   g_rank[Bsz];
__device__ int   g_cntb[Bsz];

// ---------------- helpers -------------------------------------------------
__device__ __forceinline__ void mma_f16(float c[4], const unsigned a[4],
                                        const unsigned b[2]) {
    asm volatile(
        "mma.sync.aligned.m16n8k16.row.col.f32.f16.f16.f32 "
        "{%0,%1,%2,%3}, {%4,%5,%6,%7}, {%8,%9}, {%0,%1,%2,%3};"
        : "+f"(c[0]), "+f"(c[1]), "+f"(c[2]), "+f"(c[3])
        : "r"(a[0]), "r"(a[1]), "r"(a[2]), "r"(a[3]), "r"(b[0]), "r"(b[1]));
}

__device__ __forceinline__ void ldsm_x4(unsigned r[4], uint32_t addr) {
    asm volatile("ldmatrix.sync.aligned.m8n8.x4.shared.b16 {%0,%1,%2,%3}, [%4];"
                 : "=r"(r[0]), "=r"(r[1]), "=r"(r[2]), "=r"(r[3]) : "r"(addr));
}
// B stored [N][K]: mma b-frag wants stored(n=l>>2, k=2(l&3)+{0,1}) — the
// NON-trans ldmatrix mapping.
__device__ __forceinline__ void ldsm_x2(unsigned r[2], uint32_t addr) {
    asm volatile("ldmatrix.sync.aligned.m8n8.x2.shared.b16 {%0,%1}, [%2];"
                 : "=r"(r[0]), "=r"(r[1]) : "r"(addr));
}

__device__ __forceinline__ void cpa16(uint32_t saddr, const void* g) {
    asm volatile("cp.async.cg.shared.global [%0], [%1], 16;\n"
                 :: "r"(saddr), "l"(g));
}
#define CP_COMMIT() asm volatile("cp.async.commit_group;\n" ::: "memory")
#define CP_WAIT1()  asm volatile("cp.async.wait_group 1;\n" ::: "memory")

// ---------------- FP16 tensor-core GEMM, 3-stage cp.async -----------------
// 128x128 tile, BK=32 (halfs), 256 threads (8 warps, warp tile 64x32).
// A [M][K] half, Bt [N][K] half (K-major; shared staging path).
// Smem rows of 40 halfs (80B pitch): ldmatrix row banks 20r mod 32 —
// conflict-free; rows 16B-aligned. 3 stages, one barrier per iteration.
// Labels plane is pre-zeroed by memset: MODE 3 writes ONLY the ones (rare);
// MODE 4 writes no labels at all.
// MODE 0: C = A@B + bias; z selects (A0,C0)/(A1,C1)
// MODE 2: split-K partial: z = qk*SPLITK + sk; C = C0 + z*Bsz*DIM
// MODE 3: plain; writes 1.0f into Lab where lkk[n]==lqq[m]
// MODE 4: neg scatter skipping lqq[m]'s NNq cols
#define BK    32
#define HSTR  40
#define TILEH (128 * HSTR)        // 5120 halfs per tile
#define STAGEH (2 * TILEH)        // 10240 halfs per stage (A + B)
#define SMEM_BYTES (3 * STAGEH * 2)   // 61440
template <int MODE>
__global__ __launch_bounds__(256, 2) void hgemm_k(
    const __half* __restrict__ A0, const __half* __restrict__ A1,
    const __half* __restrict__ Bt, const float* __restrict__ bias,
    float* __restrict__ C0, float* __restrict__ C1,
    int K, int ldc,
    const int* __restrict__ lqq, const int* __restrict__ lkk,
    float* __restrict__ Lab)
{
    extern __shared__ __align__(16) __half smem[];

    const int tid   = threadIdx.x;
    const int mBase = blockIdx.y * 128;
    const int nBase = blockIdx.x * 128;
    const int lane  = tid & 31;
    const int warp  = tid >> 5;
    const int g     = lane >> 2;
    const int tig   = lane & 3;
    const int wm    = (warp & 1) * 64;
    const int wn    = (warp >> 1) * 32;

    int kBeg = 0, kEnd = K;
    const __half* A;
    float* Cc;
    if (MODE == 2) {
        int qk  = blockIdx.z >> 4;
        int skc = blockIdx.z & 15;
        kBeg = skc * (K / SPLITK);
        kEnd = kBeg + K / SPLITK;
        A  = qk ? A1 : A0;
        Cc = C0 + (size_t)blockIdx.z * ((size_t)Bsz * DIM);
    } else {
        A  = blockIdx.z ? A1 : A0;
        Cc = blockIdx.z ? C1 : C0;
    }

    uint32_t sbase = (uint32_t)__cvta_generic_to_shared(smem);

    // ldmatrix per-lane address components
    const int a_row = wm + (lane & 7) + ((lane >> 3) & 1) * 8;  // + mt*16
    const int a_kof = (lane >> 4) << 3;                         // 0 or 8
    const int b_row = wn + (lane & 7);                          // + nt*8
    const int b_kof = ((lane >> 3) & 1) << 3;                   // 0 or 8

    // staging: each row = 32 halfs = 4 x 16B chunks; 2 threads/row, 2 each
    const int sr = tid >> 1;
    const int cb = (tid & 1) * 2;
    auto load_tiles = [&](int s, int kpos) {
        const __half* srcA = A  + (size_t)(mBase + sr) * K + kpos;
        const __half* srcB = Bt + (size_t)(nBase + sr) * K + kpos;
        uint32_t rowA = sbase + (uint32_t)((s * STAGEH + sr * HSTR) * 2);
        uint32_t rowB = rowA + (uint32_t)(TILEH * 2);
        #pragma unroll
        for (int i = 0; i < 2; i++) {
            int c = cb + i;
            cpa16(rowA + (uint32_t)(c * 16), srcA + c * 8);
            cpa16(rowB + (uint32_t)(c * 16), srcB + c * 8);
        }
    };

    float acc[4][4][4] = {};

    const int nIter = (kEnd - kBeg) / BK;
    load_tiles(0, kBeg);
    CP_COMMIT();
    if (nIter > 1) load_tiles(1, kBeg + BK);
    CP_COMMIT();

    for (int it = 0; it < nIter; ++it) {
        CP_WAIT1();            // stage it retired (tail groups are empty)
        __syncthreads();       // publish stage it; retire reads of (it+2)%3
        if (it + 2 < nIter) load_tiles((it + 2) % 3, kBeg + (it + 2) * BK);
        CP_COMMIT();

        const uint32_t aS = sbase + (uint32_t)((it % 3) * STAGEH * 2);
        const uint32_t bS = aS + (uint32_t)(TILEH * 2);
        #pragma unroll
        for (int kk = 0; kk < BK; kk += 16) {
            unsigned af[4][4], bf[4][2];
            #pragma unroll
            for (int mt = 0; mt < 4; mt++)
                ldsm_x4(af[mt],
                        aS + (uint32_t)(((a_row + mt * 16) * HSTR + kk + a_kof) * 2));
            #pragma unroll
            for (int nt = 0; nt < 4; nt++)
                ldsm_x2(bf[nt],
                        bS + (uint32_t)(((b_row + nt * 8) * HSTR + kk + b_kof) * 2));
            #pragma unroll
            for (int mt = 0; mt < 4; mt++)
                #pragma unroll
                for (int nt = 0; nt < 4; nt++)
                    mma_f16(acc[mt][nt], af[mt], bf[nt]);
        }
    }
    __syncthreads();

    // ---- epilogue ----
    #pragma unroll
    for (int mt = 0; mt < 4; mt++) {
        int r0 = mBase + wm + mt * 16 + g;
        int r1 = r0 + 8;
        int la0 = 0, la1 = 0, lb0 = 0, lb1 = 0;
        if (MODE == 4) { la0 = lqq[r0] * NNq; la1 = lqq[r1] * NNq; }
        if (MODE == 3) { lb0 = lqq[r0]; lb1 = lqq[r1]; }
        #pragma unroll
        for (int nt = 0; nt < 4; nt++) {
            int c = nBase + wn + nt * 8 + 2 * tig;
            const float* a4 = acc[mt][nt];
            if (MODE == 4) {
                int n0 = c, n1 = c + 1;
                if (n0 < la0)             Cc[(size_t)r0 * ldc + n0]       = a4[0];
                else if (n0 >= la0 + NNq) Cc[(size_t)r0 * ldc + n0 - NNq] = a4[0];
                if (n1 < la0)             Cc[(size_t)r0 * ldc + n1]       = a4[1];
                else if (n1 >= la0 + NNq) Cc[(size_t)r0 * ldc + n1 - NNq] = a4[1];
                if (n0 < la1)             Cc[(size_t)r1 * ldc + n0]       = a4[2];
                else if (n0 >= la1 + NNq) Cc[(size_t)r1 * ldc + n0 - NNq] = a4[2];
                if (n1 < la1)             Cc[(size_t)r1 * ldc + n1]       = a4[3];
                else if (n1 >= la1 + NNq) Cc[(size_t)r1 * ldc + n1 - NNq] = a4[3];
            } else {
                float bx = 0.f, by = 0.f;
                if (MODE == 0) { bx = bias[c]; by = bias[c + 1]; }
                float2 v0 = { a4[0] + bx, a4[1] + by };
                float2 v1 = { a4[2] + bx, a4[3] + by };
                *(float2*)(Cc + (size_t)r0 * ldc + c) = v0;
                *(float2*)(Cc + (size_t)r1 * ldc + c) = v1;
                if (MODE == 3) {
                    // labels plane pre-zeroed: store only the rare ones
                    int k0c = lkk[c], k1c = lkk[c + 1];
                    if (k0c == lb0) Lab[(size_t)r0 * ldc + c]     = 1.f;
                    if (k1c == lb0) Lab[(size_t)r0 * ldc + c + 1] = 1.f;
                    if (k0c == lb1) Lab[(size_t)r1 * ldc + c]     = 1.f;
                    if (k1c == lb1) Lab[(size_t)r1 * ldc + c + 1] = 1.f;
                }
            }
        }
    }
}

// ---------------- prep: fp32 -> fp16 (8 / thread; q/k via z) ---------------
__global__ void cvt_half_k(const float* __restrict__ in0, const float* __restrict__ in1,
                           __half* __restrict__ o0, __half* __restrict__ o1, int n8)
{
    const float* in = blockIdx.z ? in1 : in0;
    __half* o = blockIdx.z ? o1 : o0;
    int i = blockIdx.x * blockDim.x + threadIdx.x;
    if (i >= n8) return;
    float4 a = ((const float4*)in)[i * 2];
    float4 b = ((const float4*)in)[i * 2 + 1];
    __half h[8];
    h[0] = __float2half_rn(a.x); h[1] = __float2half_rn(a.y);
    h[2] = __float2half_rn(a.z); h[3] = __float2half_rn(a.w);
    h[4] = __float2half_rn(b.x); h[5] = __float2half_rn(b.y);
    h[6] = __float2half_rn(b.z); h[7] = __float2half_rn(b.w);
    ((uint4*)o)[i] = *(const uint4*)h;
}

// ---------------- prep: transpose fp32 [R][C] -> half [C][R] ---------------
__global__ void transpose_half_k(const float* __restrict__ in, __half* __restrict__ out,
                                 int R, int C)
{
    __shared__ float t[32][33];
    int cx = blockIdx.x * 32 + threadIdx.x;
    int ry = blockIdx.y * 32 + threadIdx.y;
    #pragma unroll
    for (int j = 0; j < 32; j += 8)
        t[threadIdx.y + j][threadIdx.x] = in[(size_t)(ry + j) * C + cx];
    __syncthreads();
    int cx2 = blockIdx.y * 32 + threadIdx.x;
    int ry2 = blockIdx.x * 32 + threadIdx.y;
    #pragma unroll
    for (int j = 0; j < 32; j += 8)
        out[(size_t)(ry2 + j) * R + cx2] = __float2half_rn(t[threadIdx.x][threadIdx.y + j]);
}

// ---------------- BN stats -------------------------------------------------
__global__ void bn_stats_k(const float* __restrict__ Hq, const float* __restrict__ Hk,
                           const float* __restrict__ gamma, const float* __restrict__ beta,
                           float* __restrict__ scq, float* __restrict__ shq,
                           float* __restrict__ sck, float* __restrict__ shk)
{
    const float* H = blockIdx.z ? Hk : Hq;
    float* scale = blockIdx.z ? sck : scq;
    float* shift = blockIdx.z ? shk : shq;
    int f = blockIdx.x * 32 + threadIdx.x;
    float s = 0.f, ss = 0.f;
    for (int r = threadIdx.y; r < Bsz; r += 32) {
        float v = H[(size_t)r * DF + f];
        s += v; ss += v * v;
    }
    __shared__ float sh_s[32][33], sh_ss[32][33];
    sh_s[threadIdx.y][threadIdx.x]  = s;
    sh_ss[threadIdx.y][threadIdx.x] = ss;
    __syncthreads();
    if (threadIdx.y == 0) {
        #pragma unroll
        for (int y = 1; y < 32; y++) {
            s += sh_s[y][threadIdx.x]; ss += sh_ss[y][threadIdx.x];
        }
        float mu  = s * (1.f / Bsz);
        float var = ss * (1.f / Bsz) - mu * mu;
        float rst = rsqrtf(var + 1e-5f);
        float scv = rst * gamma[f];
        scale[f] = scv;
        shift[f] = beta[f] - mu * scv;
    }
}

// ---------------- BN apply + relu -> half ----------------------------------
__global__ void bnrelu_half_k(const float* __restrict__ Hq, const float* __restrict__ Hk,
                              __half* __restrict__ Rq, __half* __restrict__ Rk)
{
    const float* H = blockIdx.z ? Hk : Hq;
    __half* R = blockIdx.z ? Rk : Rq;
    const float* sc = blockIdx.z ? g_sck : g_scq;
    const float* sh = blockIdx.z ? g_shk : g_shq;
    int i = blockIdx.x * blockDim.x + threadIdx.x;   // 8-float group
    int f = (i * 8) & (DF - 1);
    float4 a = ((const float4*)H)[i * 2];
    float4 b = ((const float4*)H)[i * 2 + 1];
    float4 sa = *(const float4*)(sc + f);
    float4 sb = *(const float4*)(sc + f + 4);
    float4 ha = *(const float4*)(sh + f);
    float4 hb = *(const float4*)(sh + f + 4);
    __half h[8];
    h[0] = __float2half_rn(fmaxf(fmaf(a.x, sa.x, ha.x), 0.f));
    h[1] = __float2half_rn(fmaxf(fmaf(a.y, sa.y, ha.y), 0.f));
    h[2] = __float2half_rn(fmaxf(fmaf(a.z, sa.z, ha.z), 0.f));
    h[3] = __float2half_rn(fmaxf(fmaf(a.w, sa.w, ha.w), 0.f));
    h[4] = __float2half_rn(fmaxf(fmaf(b.x, sb.x, hb.x), 0.f));
    h[5] = __float2half_rn(fmaxf(fmaf(b.y, sb.y, hb.y), 0.f));
    h[6] = __float2half_rn(fmaxf(fmaf(b.z, sb.z, hb.z), 0.f));
    h[7] = __float2half_rn(fmaxf(fmaf(b.w, sb.w, hb.w), 0.f));
    ((uint4*)R)[i] = *(const uint4*)h;
}

// ---------------- split-K reduce + bias + l2norm ---------------------------
__global__ void reduce_l2_k(const float* __restrict__ b2)
{
    int qk = blockIdx.y, b = blockIdx.x, d = threadIdx.x;  // d: 0..127
    const float* part = g_fpart + (size_t)qk * SPLITK * Bsz * DIM;
    float v = b2[d];
    #pragma unroll
    for (int s = 0; s < SPLITK; s++)
        v += part[(size_t)s * Bsz * DIM + (size_t)b * DIM + d];
    float ss = v * v;
    #pragma unroll
    for (int o = 16; o; o >>= 1) ss += __shfl_xor_sync(0xffffffffu, ss, o);
    __shared__ float ws[4];
    if ((d & 31) == 0) ws[d >> 5] = ss;
    __syncthreads();
    ss = ws[0] + ws[1] + ws[2] + ws[3];
    float inv = 1.f / fmaxf(sqrtf(ss), 1e-12f);
    float vn = v * inv;
    if (qk) {
        g_featk[(size_t)b * DIM + d] = vn;
        g_featkH[(size_t)b * DIM + d] = __float2half_rn(vn);
    } else {
        g_featq[(size_t)b * DIM + d] = vn;
        g_featqH[(size_t)b * DIM + d] = __float2half_rn(vn);
    }
}

// ---------------- pos_list (+ ones into labels) ----------------------------
__global__ void pos_k(const int* __restrict__ lq, const float* __restrict__ posq,
                      float* __restrict__ out)
{
    int b = blockIdx.x, tid = threadIdx.x;
    __shared__ float fr[DIM];
    if (tid < DIM) fr[tid] = g_featq[(size_t)b * DIM + tid];
    __syncthreads();
    int w = tid >> 5, lane = tid & 31;
    int col = lq[b] * PP + w;
    float s = 0.f;
    for (int d = lane; d < DIM; d += 32)
        s += fr[d] * posq[(size_t)d * PC + col];
    #pragma unroll
    for (int o = 16; o; o >>= 1) s += __shfl_down_sync(0xffffffffu, s, o);
    if (lane == 0) {
        out[OFF_SIM + (size_t)b * SIMW + Bsz + w] = s;
        out[OFF_LAB + (size_t)b * SIMW + Bsz + w] = 1.f;
    }
}

// ---------------- occurrence rank + count (warp-per-row) -------------------
__global__ void rank_k(const int* __restrict__ lk)
{
    __shared__ int sl[Bsz];
    int t = threadIdx.y * 32 + threadIdx.x;
    for (int i = t; i < Bsz; i += 1024) sl[i] = lk[i];
    __syncthreads();
    int b = blockIdx.x * 32 + threadIdx.y;
    int lab = sl[b];
    int r = 0, c = 0;
    for (int j = threadIdx.x; j < Bsz; j += 32) {
        int e = (sl[j] == lab);
        c += e;
        r += e & (j < b);
    }
    #pragma unroll
    for (int o = 16; o; o >>= 1) {
        c += __shfl_down_sync(0xffffffffu, c, o);
        r += __shfl_down_sync(0xffffffffu, r, o);
    }
    if (threadIdx.x == 0) { g_rank[b] = r; g_cntb[b] = c; }
}

// ---------------- ptr outputs (warp-per-class) -----------------------------
__global__ void ptr_k(const int* __restrict__ lk, const int* __restrict__ nptr,
                      const int* __restrict__ pptr, float* __restrict__ out)
{
    __shared__ int sl[Bsz];
    for (int i = threadIdx.x; i < Bsz; i += 256) sl[i] = lk[i];
    __syncthreads();
    int w = threadIdx.x >> 5, lane = threadIdx.x & 31;
    int c = blockIdx.x * 8 + w;
    int cnt = 0;
    for (int j = lane; j < Bsz; j += 32) cnt += (sl[j] == c);
    #pragma unroll
    for (int o = 16; o; o >>= 1) cnt += __shfl_down_sync(0xffffffffu, cnt, o);
    if (lane == 0) {
        out[OFF_NPTR + c] = (float)((nptr[c] + cnt) % NNq);
        out[OFF_PPTR + c] = (float)((pptr[c] + cnt) % PP);
    }
}

// ---------------- queue overwrite ------------------------------------------
__global__ void queue_update_k(const int* __restrict__ lk, const int* __restrict__ nptr,
                               const int* __restrict__ pptr, float* __restrict__ out)
{
    int b = blockIdx.x;
    int d = threadIdx.x;   // 128
    int lab = lk[b];
    int r = g_rank[b];
    int c = g_cntb[b];
    float v = g_featk[(size_t)b * DIM + d];
    if (r >= c - NNq) {
        int slot = (nptr[lab] + r) % NNq;
        out[OFF_NQ2 + (size_t)d * NC + lab * NNq + slot] = v;
    }
    if (r >= c - PP) {
        int slot = (pptr[lab] + r) % PP;
        out[OFF_PQ2 + (size_t)d * PC + lab * PP + slot] = v;
    }
}

// ---------------- host launcher --------------------------------------------
static void* symp(const void* sym) {
    void* p = nullptr;
    cudaGetSymbolAddress(&p, sym);
    return p;
}

extern "C" void kernel_launch(void* const* d_in, const int* in_sizes, int n_in,
                              void* d_out, int out_size)
{
    (void)in_sizes; (void)n_in; (void)out_size;
    const float* midq  = (const float*)d_in[0];
    const float* midk  = (const float*)d_in[1];
    const int*   lq    = (const int*)d_in[2];
    const int*   lk    = (const int*)d_in[3];
    const float* W1    = (const float*)d_in[4];
    const float* b1    = (const float*)d_in[5];
    const float* gamma = (const float*)d_in[6];
    const float* beta  = (const float*)d_in[7];
    const float* W2    = (const float*)d_in[8];
    const float* b2    = (const float*)d_in[9];
    const float* Wlin  = (const float*)d_in[10];
    const float* blin  = (const float*)d_in[11];
    const float* negq  = (const float*)d_in[12];
    const float* posq  = (const float*)d_in[13];
    const int*   nptr  = (const int*)d_in[14];
    const int*   pptr  = (const int*)d_in[15];
    float* out = (float*)d_out;

    float*  Hq     = (float*)symp(g_Hq);
    float*  Hk     = (float*)symp(g_Hk);
    __half* midqH  = (__half*)symp(g_midqH);
    __half* midkH  = (__half*)symp(g_midkH);
    __half* HqH    = (__half*)symp(g_HqH);
    __half* HkH    = (__half*)symp(g_HkH);
    __half* W1T    = (__half*)symp(g_W1T);
    __half* WlinT  = (__half*)symp(g_WlinT);
    __half* W2T    = (__half*)symp(g_W2T);
    __half* negT   = (__half*)symp(g_negT);
    float*  scq = (float*)symp(g_scq); float* shq = (float*)symp(g_shq);
    float*  sck = (float*)symp(g_sck); float* shk = (float*)symp(g_shk);
    __half* fqH = (__half*)symp(g_featqH);
    __half* fkH = (__half*)symp(g_featkH);
    float*  fpart = (float*)symp(g_fpart);

    cudaFuncSetAttribute(hgemm_k<0>, cudaFuncAttributeMaxDynamicSharedMemorySize, SMEM_BYTES);
    cudaFuncSetAttribute(hgemm_k<2>, cudaFuncAttributeMaxDynamicSharedMemorySize, SMEM_BYTES);
    cudaFuncSetAttribute(hgemm_k<3>, cudaFuncAttributeMaxDynamicSharedMemorySize, SMEM_BYTES);
    cudaFuncSetAttribute(hgemm_k<4>, cudaFuncAttributeMaxDynamicSharedMemorySize, SMEM_BYTES);

    // static fork stream + events (created once, outside graph capture)
    static cudaStream_t s2 = nullptr;
    static cudaEvent_t evFork = nullptr, evJoin = nullptr, evLab = nullptr,
                       evFeat = nullptr;
    if (!s2) {
        cudaStreamCreateWithFlags(&s2, cudaStreamNonBlocking);
        cudaEventCreateWithFlags(&evFork, cudaEventDisableTiming);
        cudaEventCreateWithFlags(&evJoin, cudaEventDisableTiming);
        cudaEventCreateWithFlags(&evLab, cudaEventDisableTiming);
        cudaEventCreateWithFlags(&evFeat, cudaEventDisableTiming);
    }

    // ---- default stream: prep shared by both branches ----
    cvt_half_k<<<dim3(Bsz * DF / 8 / 256, 1, 2), 256>>>(
        midq, midk, midqH, midkH, Bsz * DF / 8);
    transpose_half_k<<<dim3(CC / 32, DF / 32), dim3(32, 8)>>>(Wlin, WlinT, DF, CC);

    // ---- fork: s2 zeroes labels, copies queues, runs the Wlin GEMM ----
    cudaEventRecord(evFork, 0);
    cudaStreamWaitEvent(s2, evFork, 0);
    cudaMemsetAsync(out + OFF_LAB, 0, sizeof(float) * (size_t)Bsz * SIMW, s2);
    cudaEventRecord(evLab, s2);
    cudaMemcpyAsync(out + OFF_NQ2, negq, sizeof(float) * (size_t)DIM * NC,
                    cudaMemcpyDeviceToDevice, s2);
    cudaMemcpyAsync(out + OFF_PQ2, posq, sizeof(float) * (size_t)DIM * PC,
                    cudaMemcpyDeviceToDevice, s2);
    hgemm_k<0><<<dim3(CC / 128, Bsz / 128, 2), 256, SMEM_BYTES, s2>>>(
        midqH, midkH, WlinT, blin, out + OFF_LQ, out + OFF_LK,
        DF, CC, nullptr, nullptr, nullptr);

    // ---- default stream: the dependency chain ----
    transpose_half_k<<<dim3(DF / 32, DF / 32), dim3(32, 8)>>>(W1, W1T, DF, DF);
    transpose_half_k<<<dim3(DIM / 32, DF / 32), dim3(32, 8)>>>(W2, W2T, DF, DIM);
    transpose_half_k<<<dim3(NC / 32, DIM / 32), dim3(32, 8)>>>(negq, negT, DIM, NC);

    // H = mid @ W1 + b1
    hgemm_k<0><<<dim3(DF / 128, Bsz / 128, 2), 256, SMEM_BYTES>>>(
        midqH, midkH, W1T, b1, Hq, Hk, DF, DF, nullptr, nullptr, nullptr);

    // BN stats + apply(relu) -> half
    bn_stats_k<<<dim3(DF / 32, 1, 2), dim3(32, 32)>>>(
        Hq, Hk, gamma, beta, scq, shq, sck, shk);
    bnrelu_half_k<<<dim3(Bsz * DF / 8 / 256, 1, 2), 256>>>(Hq, Hk, HqH, HkH);

    // feat partials = relu(BN(H)) @ W2 (split-K 16, q/k via z)
    hgemm_k<2><<<dim3(1, Bsz / 128, 2 * SPLITK), 256, SMEM_BYTES>>>(
        HqH, HkH, W2T, nullptr, fpart, nullptr, DF, DIM,
        nullptr, nullptr, nullptr);

    // reduce + bias + l2norm (fp32 + half feats)
    reduce_l2_k<<<dim3(Bsz, 2), DIM>>>(b2);
    cudaEventRecord(evFeat, 0);   // feats + negT ready (stream order)

    // ---- s2: neg GEMM overlaps sim/pos/rank/ptr on default ----
    cudaStreamWaitEvent(s2, evFeat, 0);
    hgemm_k<4><<<dim3(NC / 128, Bsz / 128, 1), 256, SMEM_BYTES, s2>>>(
        fqH, nullptr, negT, nullptr, out + OFF_SIM + Bsz + PP, nullptr,
        DIM, SIMW, lq, nullptr, nullptr);
    cudaEventRecord(evJoin, s2);

    // labels plane must be zeroed before the sparse ones are written
    cudaStreamWaitEvent(0, evLab, 0);

    // sim_batch = feat_q @ feat_k^T (+ sparse label ones)
    hgemm_k<3><<<dim3(Bsz / 128, Bsz / 128, 1), 256, SMEM_BYTES>>>(
        fqH, nullptr, fkH, nullptr, out + OFF_SIM, nullptr, DIM, SIMW,
        lq, lk, out + OFF_LAB);

    // pos_list (+ ones)
    pos_k<<<Bsz, 256>>>(lq, posq, out);

    // queue update machinery
    rank_k<<<32, dim3(32, 32)>>>(lk);
    ptr_k<<<CC / 8, 256>>>(lk, nptr, pptr, out);
    cudaStreamWaitEvent(0, evJoin, 0);   // join s2 (neg + copies) back
    queue_update_k<<<Bsz, DIM>>>(lk, nptr, pptr, out);
}

// round 17
// speedup vs baseline: 1.2607x; 1.0246x over previous
#include <cuda_runtime.h>
#include <cuda_fp16.h>
#include <cstddef>
#include <cstdint>

#define Bsz   1024
#define DF    2048
#define DIM   128
#define CC    8192
#define PP    8
#define NNq   4
#define NC    (NNq * CC)            // 32768
#define PC    (PP * CC)             // 65536
#define SIMW  (Bsz + PP + NNq * (CC - 1))  // 33796
#define SPLITK 16

static constexpr size_t OFF_SIM  = 0;
static constexpr size_t OFF_LAB  = (size_t)Bsz * SIMW;
static constexpr size_t OFF_LQ   = OFF_LAB + (size_t)Bsz * SIMW;
static constexpr size_t OFF_LK   = OFF_LQ + (size_t)Bsz * CC;
static constexpr size_t OFF_NQ2  = OFF_LK + (size_t)Bsz * CC;
static constexpr size_t OFF_PQ2  = OFF_NQ2 + (size_t)DIM * NC;
static constexpr size_t OFF_NPTR = OFF_PQ2 + (size_t)DIM * PC;
static constexpr size_t OFF_PPTR = OFF_NPTR + CC;

// ---------------- device scratch (16B-aligned for cp.async) ---------------
__device__ __align__(16) float  g_Hq[(size_t)Bsz * DF];
__device__ __align__(16) float  g_Hk[(size_t)Bsz * DF];
__device__ __align__(16) __half g_midqH[(size_t)Bsz * DF];
__device__ __align__(16) __half g_midkH[(size_t)Bsz * DF];
__device__ __align__(16) __half g_HqH[(size_t)Bsz * DF];     // relu(BN(H)) half
__device__ __align__(16) __half g_HkH[(size_t)Bsz * DF];
__device__ __align__(16) __half g_W1T[(size_t)DF * DF];      // [N][K] half
__device__ __align__(16) __half g_WlinT[(size_t)CC * DF];
__device__ __align__(16) __half g_W2T[(size_t)DIM * DF];
__device__ __align__(16) __half g_negT[(size_t)NC * DIM];
__device__ float g_scq[DF], g_shq[DF], g_sck[DF], g_shk[DF];
__device__ float g_featq[(size_t)Bsz * DIM];
__device__ float g_featk[(size_t)Bsz * DIM];
__device__ __align__(16) __half g_featqH[(size_t)Bsz * DIM];
__device__ __align__(16) __half g_featkH[(size_t)Bsz * DIM];
__device__ float g_fpart[(size_t)2 * SPLITK * Bsz * DIM];
__device__ int   g_rank[Bsz];
__device__ int   g_cntb[Bsz];

// ---------------- helpers -------------------------------------------------
__device__ __forceinline__ void mma_f16(float c[4], const unsigned a[4],
                                        const unsigned b[2]) {
    asm volatile(
        "mma.sync.aligned.m16n8k16.row.col.f32.f16.f16.f32 "
        "{%0,%1,%2,%3}, {%4,%5,%6,%7}, {%8,%9}, {%0,%1,%2,%3};"
        : "+f"(c[0]), "+f"(c[1]), "+f"(c[2]), "+f"(c[3])
        : "r"(a[0]), "r"(a[1]), "r"(a[2]), "r"(a[3]), "r"(b[0]), "r"(b[1]));
}

__device__ __forceinline__ void ldsm_x4(unsigned r[4], uint32_t addr) {
    asm volatile("ldmatrix.sync.aligned.m8n8.x4.shared.b16 {%0,%1,%2,%3}, [%4];"
                 : "=r"(r[0]), "=r"(r[1]), "=r"(r[2]), "=r"(r[3]) : "r"(addr));
}
// B stored [N][K]: mma b-frag wants stored(n=l>>2, k=2(l&3)+{0,1}) — the
// NON-trans ldmatrix mapping.
__device__ __forceinline__ void ldsm_x2(unsigned r[2], uint32_t addr) {
    asm volatile("ldmatrix.sync.aligned.m8n8.x2.shared.b16 {%0,%1}, [%2];"
                 : "=r"(r[0]), "=r"(r[1]) : "r"(addr));
}

__device__ __forceinline__ void cpa16(uint32_t saddr, const void* g) {
    asm volatile("cp.async.cg.shared.global [%0], [%1], 16;\n"
                 :: "r"(saddr), "l"(g));
}
#define CP_COMMIT() asm volatile("cp.async.commit_group;\n" ::: "memory")
#define CP_WAIT1()  asm volatile("cp.async.wait_group 1;\n" ::: "memory")

// ---------------- FP16 tensor-core GEMM, 3-stage cp.async -----------------
// 128x128 tile, BK=32 (halfs), 256 threads (8 warps, warp tile 64x32).
// A [M][K] half, Bt [N][K] half (K-major; shared staging path).
// Smem rows of 40 halfs (80B pitch): ldmatrix row banks 20r mod 32 —
// conflict-free; rows 16B-aligned. 3 stages, one barrier per iteration.
// Labels plane is pre-zeroed by memset: MODE 3 writes ONLY the ones (rare);
// MODE 4 writes no labels at all.
// MODE 0: C = A@B + bias; z selects (A0,C0)/(A1,C1)
// MODE 2: split-K partial: z = qk*SPLITK + sk; C = C0 + z*Bsz*DIM
// MODE 3: plain; writes 1.0f into Lab where lkk[n]==lqq[m]
// MODE 4: neg scatter skipping lqq[m]'s NNq cols
#define BK    32
#define HSTR  40
#define TILEH (128 * HSTR)        // 5120 halfs per tile
#define STAGEH (2 * TILEH)        // 10240 halfs per stage (A + B)
#define SMEM_BYTES (3 * STAGEH * 2)   // 61440
template <int MODE>
__global__ __launch_bounds__(256, 2) void hgemm_k(
    const __half* __restrict__ A0, const __half* __restrict__ A1,
    const __half* __restrict__ Bt, const float* __restrict__ bias,
    float* __restrict__ C0, float* __restrict__ C1,
    int K, int ldc,
    const int* __restrict__ lqq, const int* __restrict__ lkk,
    float* __restrict__ Lab)
{
    extern __shared__ __align__(16) __half smem[];

    const int tid   = threadIdx.x;
    const int mBase = blockIdx.y * 128;
    const int nBase = blockIdx.x * 128;
    const int lane  = tid & 31;
    const int warp  = tid >> 5;
    const int g     = lane >> 2;
    const int tig   = lane & 3;
    const int wm    = (warp & 1) * 64;
    const int wn    = (warp >> 1) * 32;

    int kBeg = 0, kEnd = K;
    const __half* A;
    float* Cc;
    if (MODE == 2) {
        int qk  = blockIdx.z >> 4;
        int skc = blockIdx.z & 15;
        kBeg = skc * (K / SPLITK);
        kEnd = kBeg + K / SPLITK;
        A  = qk ? A1 : A0;
        Cc = C0 + (size_t)blockIdx.z * ((size_t)Bsz * DIM);
    } else {
        A  = blockIdx.z ? A1 : A0;
        Cc = blockIdx.z ? C1 : C0;
    }

    uint32_t sbase = (uint32_t)__cvta_generic_to_shared(smem);

    // ldmatrix per-lane address components
    const int a_row = wm + (lane & 7) + ((lane >> 3) & 1) * 8;  // + mt*16
    const int a_kof = (lane >> 4) << 3;                         // 0 or 8
    const int b_row = wn + (lane & 7);                          // + nt*8
    const int b_kof = ((lane >> 3) & 1) << 3;                   // 0 or 8

    // staging: each row = 32 halfs = 4 x 16B chunks; 2 threads/row, 2 each
    const int sr = tid >> 1;
    const int cb = (tid & 1) * 2;
    auto load_tiles = [&](int s, int kpos) {
        const __half* srcA = A  + (size_t)(mBase + sr) * K + kpos;
        const __half* srcB = Bt + (size_t)(nBase + sr) * K + kpos;
        uint32_t rowA = sbase + (uint32_t)((s * STAGEH + sr * HSTR) * 2);
        uint32_t rowB = rowA + (uint32_t)(TILEH * 2);
        #pragma unroll
        for (int i = 0; i < 2; i++) {
            int c = cb + i;
            cpa16(rowA + (uint32_t)(c * 16), srcA + c * 8);
            cpa16(rowB + (uint32_t)(c * 16), srcB + c * 8);
        }
    };

    float acc[4][4][4] = {};

    const int nIter = (kEnd - kBeg) / BK;
    load_tiles(0, kBeg);
    CP_COMMIT();
    if (nIter > 1) load_tiles(1, kBeg + BK);
    CP_COMMIT();

    for (int it = 0; it < nIter; ++it) {
        CP_WAIT1();            // stage it retired (tail groups are empty)
        __syncthreads();       // publish stage it; retire reads of (it+2)%3
        if (it + 2 < nIter) load_tiles((it + 2) % 3, kBeg + (it + 2) * BK);
        CP_COMMIT();

        const uint32_t aS = sbase + (uint32_t)((it % 3) * STAGEH * 2);
        const uint32_t bS = aS + (uint32_t)(TILEH * 2);
        #pragma unroll
        for (int kk = 0; kk < BK; kk += 16) {
            unsigned af[4][4], bf[4][2];
            #pragma unroll
            for (int mt = 0; mt < 4; mt++)
                ldsm_x4(af[mt],
                        aS + (uint32_t)(((a_row + mt * 16) * HSTR + kk + a_kof) * 2));
            #pragma unroll
            for (int nt = 0; nt < 4; nt++)
                ldsm_x2(bf[nt],
                        bS + (uint32_t)(((b_row + nt * 8) * HSTR + kk + b_kof) * 2));
            #pragma unroll
            for (int mt = 0; mt < 4; mt++)
                #pragma unroll
                for (int nt = 0; nt < 4; nt++)
                    mma_f16(acc[mt][nt], af[mt], bf[nt]);
        }
    }
    __syncthreads();

    // ---- epilogue ----
    #pragma unroll
    for (int mt = 0; mt < 4; mt++) {
        int r0 = mBase + wm + mt * 16 + g;
        int r1 = r0 + 8;
        int la0 = 0, la1 = 0, lb0 = 0, lb1 = 0;
        if (MODE == 4) { la0 = lqq[r0] * NNq; la1 = lqq[r1] * NNq; }
        if (MODE == 3) { lb0 = lqq[r0]; lb1 = lqq[r1]; }
        #pragma unroll
        for (int nt = 0; nt < 4; nt++) {
            int c = nBase + wn + nt * 8 + 2 * tig;
            const float* a4 = acc[mt][nt];
            if (MODE == 4) {
                int n0 = c, n1 = c + 1;
                if (n0 < la0)             Cc[(size_t)r0 * ldc + n0]       = a4[0];
                else if (n0 >= la0 + NNq) Cc[(size_t)r0 * ldc + n0 - NNq] = a4[0];
                if (n1 < la0)             Cc[(size_t)r0 * ldc + n1]       = a4[1];
                else if (n1 >= la0 + NNq) Cc[(size_t)r0 * ldc + n1 - NNq] = a4[1];
                if (n0 < la1)             Cc[(size_t)r1 * ldc + n0]       = a4[2];
                else if (n0 >= la1 + NNq) Cc[(size_t)r1 * ldc + n0 - NNq] = a4[2];
                if (n1 < la1)             Cc[(size_t)r1 * ldc + n1]       = a4[3];
                else if (n1 >= la1 + NNq) Cc[(size_t)r1 * ldc + n1 - NNq] = a4[3];
            } else {
                float bx = 0.f, by = 0.f;
                if (MODE == 0) { bx = bias[c]; by = bias[c + 1]; }
                float2 v0 = { a4[0] + bx, a4[1] + by };
                float2 v1 = { a4[2] + bx, a4[3] + by };
                *(float2*)(Cc + (size_t)r0 * ldc + c) = v0;
                *(float2*)(Cc + (size_t)r1 * ldc + c) = v1;
                if (MODE == 3) {
                    // labels plane pre-zeroed: store only the rare ones
                    int k0c = lkk[c], k1c = lkk[c + 1];
                    if (k0c == lb0) Lab[(size_t)r0 * ldc + c]     = 1.f;
                    if (k1c == lb0) Lab[(size_t)r0 * ldc + c + 1] = 1.f;
                    if (k0c == lb1) Lab[(size_t)r1 * ldc + c]     = 1.f;
                    if (k1c == lb1) Lab[(size_t)r1 * ldc + c + 1] = 1.f;
                }
            }
        }
    }
}

// ---------------- prep: fp32 -> fp16 (8 / thread; q/k via z) ---------------
__global__ void cvt_half_k(const float* __restrict__ in0, const float* __restrict__ in1,
                           __half* __restrict__ o0, __half* __restrict__ o1, int n8)
{
    const float* in = blockIdx.z ? in1 : in0;
    __half* o = blockIdx.z ? o1 : o0;
    int i = blockIdx.x * blockDim.x + threadIdx.x;
    if (i >= n8) return;
    float4 a = ((const float4*)in)[i * 2];
    float4 b = ((const float4*)in)[i * 2 + 1];
    __half h[8];
    h[0] = __float2half_rn(a.x); h[1] = __float2half_rn(a.y);
    h[2] = __float2half_rn(a.z); h[3] = __float2half_rn(a.w);
    h[4] = __float2half_rn(b.x); h[5] = __float2half_rn(b.y);
    h[6] = __float2half_rn(b.z); h[7] = __float2half_rn(b.w);
    ((uint4*)o)[i] = *(const uint4*)h;
}

// ---------------- prep: transpose fp32 [R][C] -> half [C][R] ---------------
__global__ void transpose_half_k(const float* __restrict__ in, __half* __restrict__ out,
                                 int R, int C)
{
    __shared__ float t[32][33];
    int cx = blockIdx.x * 32 + threadIdx.x;
    int ry = blockIdx.y * 32 + threadIdx.y;
    #pragma unroll
    for (int j = 0; j < 32; j += 8)
        t[threadIdx.y + j][threadIdx.x] = in[(size_t)(ry + j) * C + cx];
    __syncthreads();
    int cx2 = blockIdx.y * 32 + threadIdx.x;
    int ry2 = blockIdx.x * 32 + threadIdx.y;
    #pragma unroll
    for (int j = 0; j < 32; j += 8)
        out[(size_t)(ry2 + j) * R + cx2] = __float2half_rn(t[threadIdx.x][threadIdx.y + j]);
}

// ---------------- BN stats -------------------------------------------------
__global__ void bn_stats_k(const float* __restrict__ Hq, const float* __restrict__ Hk,
                           const float* __restrict__ gamma, const float* __restrict__ beta,
                           float* __restrict__ scq, float* __restrict__ shq,
                           float* __restrict__ sck, float* __restrict__ shk)
{
    const float* H = blockIdx.z ? Hk : Hq;
    float* scale = blockIdx.z ? sck : scq;
    float* shift = blockIdx.z ? shk : shq;
    int f = blockIdx.x * 32 + threadIdx.x;
    float s = 0.f, ss = 0.f;
    for (int r = threadIdx.y; r < Bsz; r += 32) {
        float v = H[(size_t)r * DF + f];
        s += v; ss += v * v;
    }
    __shared__ float sh_s[32][33], sh_ss[32][33];
    sh_s[threadIdx.y][threadIdx.x]  = s;
    sh_ss[threadIdx.y][threadIdx.x] = ss;
    __syncthreads();
    if (threadIdx.y == 0) {
        #pragma unroll
        for (int y = 1; y < 32; y++) {
            s += sh_s[y][threadIdx.x]; ss += sh_ss[y][threadIdx.x];
        }
        float mu  = s * (1.f / Bsz);
        float var = ss * (1.f / Bsz) - mu * mu;
        float rst = rsqrtf(var + 1e-5f);
        float scv = rst * gamma[f];
        scale[f] = scv;
        shift[f] = beta[f] - mu * scv;
    }
}

// ---------------- BN apply + relu -> half ----------------------------------
__global__ void bnrelu_half_k(const float* __restrict__ Hq, const float* __restrict__ Hk,
                              __half* __restrict__ Rq, __half* __restrict__ Rk)
{
    const float* H = blockIdx.z ? Hk : Hq;
    __half* R = blockIdx.z ? Rk : Rq;
    const float* sc = blockIdx.z ? g_sck : g_scq;
    const float* sh = blockIdx.z ? g_shk : g_shq;
    int i = blockIdx.x * blockDim.x + threadIdx.x;   // 8-float group
    int f = (i * 8) & (DF - 1);
    float4 a = ((const float4*)H)[i * 2];
    float4 b = ((const float4*)H)[i * 2 + 1];
    float4 sa = *(const float4*)(sc + f);
    float4 sb = *(const float4*)(sc + f + 4);
    float4 ha = *(const float4*)(sh + f);
    float4 hb = *(const float4*)(sh + f + 4);
    __half h[8];
    h[0] = __float2half_rn(fmaxf(fmaf(a.x, sa.x, ha.x), 0.f));
    h[1] = __float2half_rn(fmaxf(fmaf(a.y, sa.y, ha.y), 0.f));
    h[2] = __float2half_rn(fmaxf(fmaf(a.z, sa.z, ha.z), 0.f));
    h[3] = __float2half_rn(fmaxf(fmaf(a.w, sa.w, ha.w), 0.f));
    h[4] = __float2half_rn(fmaxf(fmaf(b.x, sb.x, hb.x), 0.f));
    h[5] = __float2half_rn(fmaxf(fmaf(b.y, sb.y, hb.y), 0.f));
    h[6] = __float2half_rn(fmaxf(fmaf(b.z, sb.z, hb.z), 0.f));
    h[7] = __float2half_rn(fmaxf(fmaf(b.w, sb.w, hb.w), 0.f));
    ((uint4*)R)[i] = *(const uint4*)h;
}

// ---------------- split-K reduce + bias + l2norm ---------------------------
__global__ void reduce_l2_k(const float* __restrict__ b2)
{
    int qk = blockIdx.y, b = blockIdx.x, d = threadIdx.x;  // d: 0..127
    const float* part = g_fpart + (size_t)qk * SPLITK * Bsz * DIM;
    float v = b2[d];
    #pragma unroll
    for (int s = 0; s < SPLITK; s++)
        v += part[(size_t)s * Bsz * DIM + (size_t)b * DIM + d];
    float ss = v * v;
    #pragma unroll
    for (int o = 16; o; o >>= 1) ss += __shfl_xor_sync(0xffffffffu, ss, o);
    __shared__ float ws[4];
    if ((d & 31) == 0) ws[d >> 5] = ss;
    __syncthreads();
    ss = ws[0] + ws[1] + ws[2] + ws[3];
    float inv = 1.f / fmaxf(sqrtf(ss), 1e-12f);
    float vn = v * inv;
    if (qk) {
        g_featk[(size_t)b * DIM + d] = vn;
        g_featkH[(size_t)b * DIM + d] = __float2half_rn(vn);
    } else {
        g_featq[(size_t)b * DIM + d] = vn;
        g_featqH[(size_t)b * DIM + d] = __float2half_rn(vn);
    }
}

// ---------------- pos_list (+ ones into labels) ----------------------------
__global__ void pos_k(const int* __restrict__ lq, const float* __restrict__ posq,
                      float* __restrict__ out)
{
    int b = blockIdx.x, tid = threadIdx.x;
    __shared__ float fr[DIM];
    if (tid < DIM) fr[tid] = g_featq[(size_t)b * DIM + tid];
    __syncthreads();
    int w = tid >> 5, lane = tid & 31;
    int col = lq[b] * PP + w;
    float s = 0.f;
    for (int d = lane; d < DIM; d += 32)
        s += fr[d] * posq[(size_t)d * PC + col];
    #pragma unroll
    for (int o = 16; o; o >>= 1) s += __shfl_down_sync(0xffffffffu, s, o);
    if (lane == 0) {
        out[OFF_SIM + (size_t)b * SIMW + Bsz + w] = s;
        out[OFF_LAB + (size_t)b * SIMW + Bsz + w] = 1.f;
    }
}

// ---------------- occurrence rank + count (warp-per-row) -------------------
__global__ void rank_k(const int* __restrict__ lk)
{
    __shared__ int sl[Bsz];
    int t = threadIdx.y * 32 + threadIdx.x;
    for (int i = t; i < Bsz; i += 1024) sl[i] = lk[i];
    __syncthreads();
    int b = blockIdx.x * 32 + threadIdx.y;
    int lab = sl[b];
    int r = 0, c = 0;
    for (int j = threadIdx.x; j < Bsz; j += 32) {
        int e = (sl[j] == lab);
        c += e;
        r += e & (j < b);
    }
    #pragma unroll
    for (int o = 16; o; o >>= 1) {
        c += __shfl_down_sync(0xffffffffu, c, o);
        r += __shfl_down_sync(0xffffffffu, r, o);
    }
    if (threadIdx.x == 0) { g_rank[b] = r; g_cntb[b] = c; }
}

// ---------------- ptr outputs (warp-per-class) -----------------------------
__global__ void ptr_k(const int* __restrict__ lk, const int* __restrict__ nptr,
                      const int* __restrict__ pptr, float* __restrict__ out)
{
    __shared__ int sl[Bsz];
    for (int i = threadIdx.x; i < Bsz; i += 256) sl[i] = lk[i];
    __syncthreads();
    int w = threadIdx.x >> 5, lane = threadIdx.x & 31;
    int c = blockIdx.x * 8 + w;
    int cnt = 0;
    for (int j = lane; j < Bsz; j += 32) cnt += (sl[j] == c);
    #pragma unroll
    for (int o = 16; o; o >>= 1) cnt += __shfl_down_sync(0xffffffffu, cnt, o);
    if (lane == 0) {
        out[OFF_NPTR + c] = (float)((nptr[c] + cnt) % NNq);
        out[OFF_PPTR + c] = (float)((pptr[c] + cnt) % PP);
    }
}

// ---------------- queue overwrite ------------------------------------------
__global__ void queue_update_k(const int* __restrict__ lk, const int* __restrict__ nptr,
                               const int* __restrict__ pptr, float* __restrict__ out)
{
    int b = blockIdx.x;
    int d = threadIdx.x;   // 128
    int lab = lk[b];
    int r = g_rank[b];
    int c = g_cntb[b];
    float v = g_featk[(size_t)b * DIM + d];
    if (r >= c - NNq) {
        int slot = (nptr[lab] + r) % NNq;
        out[OFF_NQ2 + (size_t)d * NC + lab * NNq + slot] = v;
    }
    if (r >= c - PP) {
        int slot = (pptr[lab] + r) % PP;
        out[OFF_PQ2 + (size_t)d * PC + lab * PP + slot] = v;
    }
}

// ---------------- host launcher --------------------------------------------
static void* symp(const void* sym) {
    void* p = nullptr;
    cudaGetSymbolAddress(&p, sym);
    return p;
}

extern "C" void kernel_launch(void* const* d_in, const int* in_sizes, int n_in,
                              void* d_out, int out_size)
{
    (void)in_sizes; (void)n_in; (void)out_size;
    const float* midq  = (const float*)d_in[0];
    const float* midk  = (const float*)d_in[1];
    const int*   lq    = (const int*)d_in[2];
    const int*   lk    = (const int*)d_in[3];
    const float* W1    = (const float*)d_in[4];
    const float* b1    = (const float*)d_in[5];
    const float* gamma = (const float*)d_in[6];
    const float* beta  = (const float*)d_in[7];
    const float* W2    = (const float*)d_in[8];
    const float* b2    = (const float*)d_in[9];
    const float* Wlin  = (const float*)d_in[10];
    const float* blin  = (const float*)d_in[11];
    const float* negq  = (const float*)d_in[12];
    const float* posq  = (const float*)d_in[13];
    const int*   nptr  = (const int*)d_in[14];
    const int*   pptr  = (const int*)d_in[15];
    float* out = (float*)d_out;

    float*  Hq     = (float*)symp(g_Hq);
    float*  Hk     = (float*)symp(g_Hk);
    __half* midqH  = (__half*)symp(g_midqH);
    __half* midkH  = (__half*)symp(g_midkH);
    __half* HqH    = (__half*)symp(g_HqH);
    __half* HkH    = (__half*)symp(g_HkH);
    __half* W1T    = (__half*)symp(g_W1T);
    __half* WlinT  = (__half*)symp(g_WlinT);
    __half* W2T    = (__half*)symp(g_W2T);
    __half* negT   = (__half*)symp(g_negT);
    float*  scq = (float*)symp(g_scq); float* shq = (float*)symp(g_shq);
    float*  sck = (float*)symp(g_sck); float* shk = (float*)symp(g_shk);
    __half* fqH = (__half*)symp(g_featqH);
    __half* fkH = (__half*)symp(g_featkH);
    float*  fpart = (float*)symp(g_fpart);

    cudaFuncSetAttribute(hgemm_k<0>, cudaFuncAttributeMaxDynamicSharedMemorySize, SMEM_BYTES);
    cudaFuncSetAttribute(hgemm_k<2>, cudaFuncAttributeMaxDynamicSharedMemorySize, SMEM_BYTES);
    cudaFuncSetAttribute(hgemm_k<3>, cudaFuncAttributeMaxDynamicSharedMemorySize, SMEM_BYTES);
    cudaFuncSetAttribute(hgemm_k<4>, cudaFuncAttributeMaxDynamicSharedMemorySize, SMEM_BYTES);

    // static fork streams + events (created once, outside graph capture)
    static cudaStream_t s2 = nullptr, s3 = nullptr;
    static cudaEvent_t evFork = nullptr, evJoin = nullptr, evLab = nullptr,
                       evFeat = nullptr, evCvt = nullptr, evCopies = nullptr;
    if (!s2) {
        cudaStreamCreateWithFlags(&s2, cudaStreamNonBlocking);
        cudaStreamCreateWithFlags(&s3, cudaStreamNonBlocking);
        cudaEventCreateWithFlags(&evFork, cudaEventDisableTiming);
        cudaEventCreateWithFlags(&evJoin, cudaEventDisableTiming);
        cudaEventCreateWithFlags(&evLab, cudaEventDisableTiming);
        cudaEventCreateWithFlags(&evFeat, cudaEventDisableTiming);
        cudaEventCreateWithFlags(&evCvt, cudaEventDisableTiming);
        cudaEventCreateWithFlags(&evCopies, cudaEventDisableTiming);
    }

    // ---- fork both side streams from the origin ----
    cudaEventRecord(evFork, 0);
    cudaStreamWaitEvent(s2, evFork, 0);
    cudaStreamWaitEvent(s3, evFork, 0);

    // ---- s3: pure copy work (labels memset + queue copies) ----
    cudaMemsetAsync(out + OFF_LAB, 0, sizeof(float) * (size_t)Bsz * SIMW, s3);
    cudaEventRecord(evLab, s3);
    cudaMemcpyAsync(out + OFF_NQ2, negq, sizeof(float) * (size_t)DIM * NC,
                    cudaMemcpyDeviceToDevice, s3);
    cudaMemcpyAsync(out + OFF_PQ2, posq, sizeof(float) * (size_t)DIM * PC,
                    cudaMemcpyDeviceToDevice, s3);
    cudaEventRecord(evCopies, s3);

    // ---- s2: WlinT transpose immediately; Wlin GEMM as soon as cvt lands ----
    transpose_half_k<<<dim3(CC / 32, DF / 32), dim3(32, 8), 0, s2>>>(
        Wlin, WlinT, DF, CC);

    // ---- default: cvt (needed by both branches) ----
    cvt_half_k<<<dim3(Bsz * DF / 8 / 256, 1, 2), 256>>>(
        midq, midk, midqH, midkH, Bsz * DF / 8);
    cudaEventRecord(evCvt, 0);

    cudaStreamWaitEvent(s2, evCvt, 0);
    hgemm_k<0><<<dim3(CC / 128, Bsz / 128, 2), 256, SMEM_BYTES, s2>>>(
        midqH, midkH, WlinT, blin, out + OFF_LQ, out + OFF_LK,
        DF, CC, nullptr, nullptr, nullptr);

    // ---- default: the dependency chain ----
    transpose_half_k<<<dim3(DF / 32, DF / 32), dim3(32, 8)>>>(W1, W1T, DF, DF);
    transpose_half_k<<<dim3(DIM / 32, DF / 32), dim3(32, 8)>>>(W2, W2T, DF, DIM);
    transpose_half_k<<<dim3(NC / 32, DIM / 32), dim3(32, 8)>>>(negq, negT, DIM, NC);

    // H = mid @ W1 + b1
    hgemm_k<0><<<dim3(DF / 128, Bsz / 128, 2), 256, SMEM_BYTES>>>(
        midqH, midkH, W1T, b1, Hq, Hk, DF, DF, nullptr, nullptr, nullptr);

    // BN stats + apply(relu) -> half
    bn_stats_k<<<dim3(DF / 32, 1, 2), dim3(32, 32)>>>(
        Hq, Hk, gamma, beta, scq, shq, sck, shk);
    bnrelu_half_k<<<dim3(Bsz * DF / 8 / 256, 1, 2), 256>>>(Hq, Hk, HqH, HkH);

    // feat partials = relu(BN(H)) @ W2 (split-K 16, q/k via z)
    hgemm_k<2><<<dim3(1, Bsz / 128, 2 * SPLITK), 256, SMEM_BYTES>>>(
        HqH, HkH, W2T, nullptr, fpart, nullptr, DF, DIM,
        nullptr, nullptr, nullptr);

    // reduce + bias + l2norm (fp32 + half feats)
    reduce_l2_k<<<dim3(Bsz, 2), DIM>>>(b2);
    cudaEventRecord(evFeat, 0);   // feats + negT ready (stream order)

    // ---- s2: neg GEMM after Wlin, overlapping sim/pos/rank/ptr ----
    cudaStreamWaitEvent(s2, evFeat, 0);
    cudaStreamWaitEvent(s2, evLab, 0);   // label zeros precede (no label writes, but cheap)
    hgemm_k<4><<<dim3(NC / 128, Bsz / 128, 1), 256, SMEM_BYTES, s2>>>(
        fqH, nullptr, negT, nullptr, out + OFF_SIM + Bsz + PP, nullptr,
        DIM, SIMW, lq, nullptr, nullptr);
    cudaEventRecord(evJoin, s2);

    // labels plane must be zeroed before the sparse ones are written
    cudaStreamWaitEvent(0, evLab, 0);

    // sim_batch = feat_q @ feat_k^T (+ sparse label ones)
    hgemm_k<3><<<dim3(Bsz / 128, Bsz / 128, 1), 256, SMEM_BYTES>>>(
        fqH, nullptr, fkH, nullptr, out + OFF_SIM, nullptr, DIM, SIMW,
        lq, lk, out + OFF_LAB);

    // pos_list (+ ones)
    pos_k<<<Bsz, 256>>>(lq, posq, out);

    // queue update machinery
    rank_k<<<32, dim3(32, 32)>>>(lk);
    ptr_k<<<CC / 8, 256>>>(lk, nptr, pptr, out);
    cudaStreamWaitEvent(0, evCopies, 0); // join s3
    cudaStreamWaitEvent(0, evJoin, 0);   // join s2
    queue_update_k<<<Bsz, DIM>>>(lk, nptr, pptr, out);
}